// round 1
// baseline (speedup 1.0000x reference)
#include <cuda_runtime.h>
#include <math.h>

#define BB   16
#define TT   16
#define OO   10
#define LL   160      // T*O
#define DD   768
#define NHH  12
#define DHH  64
#define GH   14
#define GW   14
#define NTOK (BB*LL)  // 2560

// ---------------- scratch (device globals; no runtime alloc allowed) --------
__device__ float g_h  [NTOK*384];     //  3.9 MB
__device__ float g_x  [NTOK*DD];      //  7.9 MB
__device__ float g_hn [NTOK*DD];      //  7.9 MB
__device__ float g_qkv[NTOK*3*DD];    // 23.6 MB
__device__ float g_att[NTOK*DD];      //  7.9 MB
__device__ float g_ffn[NTOK*4*DD];    // 31.5 MB

// ---------------- embed stage 1: h = relu(box @ w1), K=4 --------------------
__global__ void embed_h_k(const float* __restrict__ box, const float* __restrict__ w1)
{
    int idx = blockIdx.x * blockDim.x + threadIdx.x;
    if (idx >= NTOK * 384) return;
    int m = idx / 384, j = idx - m * 384;
    const float* bx = box + m * 4;
    float acc = bx[0] * w1[j] + bx[1] * w1[384 + j] + bx[2] * w1[768 + j] + bx[3] * w1[1152 + j];
    g_h[idx] = fmaxf(acc, 0.0f);
}

// ---------------- generic tiled SGEMM: C = epilogue(A @ B) ------------------
// A: MxK row-major, B: KxN row-major. BM=BN=64, BK=16, 256 thr, 4x4 microtile.
// ACT: 0 none, 1 relu, 2 exact gelu. RESMODE: 0 none, 1 res[m*N+n], 2 res[(m%160)*N+n]
#define BM 64
#define BN 64
#define BK 16
#define PAD 68

template<int ACT, int BIAS, int RESMODE>
__global__ void gemm_k(const float* __restrict__ A, const float* __restrict__ Bm,
                       const float* __restrict__ bias, const float* __restrict__ res,
                       float* __restrict__ C, int M, int N, int K)
{
    __shared__ float As[BK * PAD];
    __shared__ float Bs[BK * PAD];
    const int tid = threadIdx.x;
    const int tx = tid & 15;         // n-group
    const int ty = tid >> 4;         // m-group
    const int m0 = blockIdx.y * BM;
    const int n0 = blockIdx.x * BN;

    const int la_m = tid >> 2;           // 0..63
    const int la_k = (tid & 3) << 2;     // 0,4,8,12
    const int lb_k = tid >> 4;           // 0..15
    const int lb_n = (tid & 15) << 2;    // 0..60

    float acc[4][4] = {};

    for (int kk = 0; kk < K; kk += BK) {
        float4 av = *reinterpret_cast<const float4*>(A + (long)(m0 + la_m) * K + kk + la_k);
        float4 bv = *reinterpret_cast<const float4*>(Bm + (long)(kk + lb_k) * N + n0 + lb_n);
        As[(la_k + 0) * PAD + la_m] = av.x;
        As[(la_k + 1) * PAD + la_m] = av.y;
        As[(la_k + 2) * PAD + la_m] = av.z;
        As[(la_k + 3) * PAD + la_m] = av.w;
        *reinterpret_cast<float4*>(Bs + lb_k * PAD + lb_n) = bv;
        __syncthreads();
#pragma unroll
        for (int k = 0; k < BK; k++) {
            float4 a4 = *reinterpret_cast<const float4*>(As + k * PAD + ty * 4);
            float4 b4 = *reinterpret_cast<const float4*>(Bs + k * PAD + tx * 4);
            float a[4] = {a4.x, a4.y, a4.z, a4.w};
            float b[4] = {b4.x, b4.y, b4.z, b4.w};
#pragma unroll
            for (int i = 0; i < 4; i++)
#pragma unroll
                for (int j = 0; j < 4; j++)
                    acc[i][j] = fmaf(a[i], b[j], acc[i][j]);
        }
        __syncthreads();
    }

#pragma unroll
    for (int i = 0; i < 4; i++) {
        int m = m0 + ty * 4 + i;
#pragma unroll
        for (int j = 0; j < 4; j++) {
            int n = n0 + tx * 4 + j;
            float v = acc[i][j];
            if (BIAS) v += bias[n];
            if (ACT == 1) v = fmaxf(v, 0.0f);
            else if (ACT == 2) v = 0.5f * v * (1.0f + erff(v * 0.70710678118654752f));
            if (RESMODE == 1) v += res[(long)m * N + n];
            else if (RESMODE == 2) v += res[(long)(m % LL) * N + n];
            C[(long)m * N + n] = v;
        }
    }
}

// ---------------- layernorm: one block per row of 768 -----------------------
__global__ void ln_k(const float* __restrict__ X, const float* __restrict__ g,
                     const float* __restrict__ b, float* __restrict__ Y)
{
    int row = blockIdx.x;
    const float* x = X + (long)row * DD;
    int tid = threadIdx.x;
    float v[3];
    float s = 0.f, sq = 0.f;
#pragma unroll
    for (int r = 0; r < 3; r++) {
        v[r] = x[tid + r * 256];
        s += v[r];
        sq += v[r] * v[r];
    }
    __shared__ float red0[8], red1[8];
#pragma unroll
    for (int off = 16; off; off >>= 1) {
        s += __shfl_down_sync(0xffffffffu, s, off);
        sq += __shfl_down_sync(0xffffffffu, sq, off);
    }
    if ((tid & 31) == 0) { red0[tid >> 5] = s; red1[tid >> 5] = sq; }
    __syncthreads();
    s = 0.f; sq = 0.f;
#pragma unroll
    for (int i = 0; i < 8; i++) { s += red0[i]; sq += red1[i]; }
    float mean = s * (1.0f / DD);
    float var = sq * (1.0f / DD) - mean * mean;
    float rstd = rsqrtf(var + 1e-5f);
#pragma unroll
    for (int r = 0; r < 3; r++) {
        int c = tid + r * 256;
        Y[(long)row * DD + c] = (v[r] - mean) * rstd * g[c] + b[c];
    }
}

// ---------------- attention: one block per (b,h), 256 threads ---------------
// smem: Ks[160*65] Vs[160*65] Ps[8*160] Qs[8*64] = 90368 bytes
__global__ void attn_k(const float* __restrict__ qkv, float* __restrict__ Yo)
{
    extern __shared__ float sm[];
    float* Ks = sm;
    float* Vs = Ks + LL * 65;
    float* Ps = Vs + LL * 65;
    float* Qs = Ps + 8 * LL;

    int bh = blockIdx.x;
    int b = bh / NHH, h = bh - b * NHH;
    int tid = threadIdx.x;

    // stage K,V
    for (int idx = tid; idx < LL * DHH; idx += 256) {
        int j = idx >> 6, d = idx & 63;
        long base = (long)(b * LL + j) * 2304 + h * 64 + d;
        Ks[j * 65 + d] = qkv[base + 768];
        Vs[j * 65 + d] = qkv[base + 1536];
    }
    __syncthreads();

    int w = tid >> 5, ln = tid & 31;
    float* ps = Ps + w * LL;
    float* qs = Qs + w * 64;

    for (int r = w; r < LL; r += 8) {
        long qb = (long)(b * LL + r) * 2304 + h * 64;
        qs[ln]      = qkv[qb + ln];
        qs[ln + 32] = qkv[qb + ln + 32];
        __syncwarp();
        float sc[5];
#pragma unroll
        for (int k5 = 0; k5 < 5; k5++) {
            int j = ln + k5 * 32;
            float a = 0.f;
#pragma unroll 8
            for (int d = 0; d < 64; d++) a = fmaf(qs[d], Ks[j * 65 + d], a);
            sc[k5] = a * 0.125f;
        }
        float mx = sc[0];
#pragma unroll
        for (int k5 = 1; k5 < 5; k5++) mx = fmaxf(mx, sc[k5]);
#pragma unroll
        for (int off = 16; off; off >>= 1) mx = fmaxf(mx, __shfl_xor_sync(0xffffffffu, mx, off));
        float sum = 0.f;
#pragma unroll
        for (int k5 = 0; k5 < 5; k5++) { sc[k5] = __expf(sc[k5] - mx); sum += sc[k5]; }
#pragma unroll
        for (int off = 16; off; off >>= 1) sum += __shfl_xor_sync(0xffffffffu, sum, off);
        float inv = 1.0f / sum;
#pragma unroll
        for (int k5 = 0; k5 < 5; k5++) ps[ln + k5 * 32] = sc[k5] * inv;
        __syncwarp();
        float o0 = 0.f, o1 = 0.f;
#pragma unroll 8
        for (int j = 0; j < LL; j++) {
            float p = ps[j];
            o0 = fmaf(p, Vs[j * 65 + ln], o0);
            o1 = fmaf(p, Vs[j * 65 + ln + 32], o1);
        }
        long ob = (long)(b * LL + r) * DD + h * 64;
        Yo[ob + ln] = o0;
        Yo[ob + ln + 32] = o1;
        __syncwarp();
    }
}

// ---------------- box-mask scatter + temporal mean ---------------------------
// one block per output cell (b, tg, h, w); 256 threads over d=768 (3 each)
__global__ void grid_k(const float* __restrict__ box, float* __restrict__ out)
{
    int blk = blockIdx.x;
    int w = blk % GW;
    int hh = (blk / GW) % GH;
    int tg = (blk / (GW * GH)) & 7;
    int b = blk / (GW * GH * 8);
    int tid = threadIdx.x;

    __shared__ float flg[20];
    if (tid < 20) {
        int t = tg * 2 + tid / 10;
        int o = tid % 10;
        const float* bx = box + (long)((b * TT + t) * OO + o) * 4;
        float x1 = fminf(bx[0], bx[2]), x2 = fmaxf(bx[0], bx[2]);
        float y1 = fminf(bx[1], bx[3]), y2 = fmaxf(bx[1], bx[3]);
        float cy = (hh + 0.5f) / 14.0f;
        float cx = (w + 0.5f) / 14.0f;
        flg[tid] = (cy >= y1 && cy <= y2 && cx >= x1 && cx <= x2) ? 1.0f : 0.0f;
    }
    __syncthreads();

    float a0 = 0.f, a1 = 0.f, a2 = 0.f;
#pragma unroll
    for (int e = 0; e < 20; e++) {
        if (flg[e] > 0.f) {
            const float* f = g_x + (long)(b * LL + (tg * 2 + e / 10) * OO + (e % 10)) * DD + tid;
            a0 += f[0];
            a1 += f[256];
            a2 += f[512];
        }
    }
    long ob = (long)blk * DD + tid;     // blk ordering == (b,tg,h,w) == output layout
    out[ob]       = 0.5f * a0;
    out[ob + 256] = 0.5f * a1;
    out[ob + 512] = 0.5f * a2;
}

// ---------------- launch ------------------------------------------------------
extern "C" void kernel_launch(void* const* d_in, const int* in_sizes, int n_in,
                              void* d_out, int out_size)
{
    const float* box  = (const float*)d_in[0];
    const float* cat  = (const float*)d_in[1];
    const float* w1   = (const float*)d_in[2];
    const float* w2   = (const float*)d_in[3];
    const float* ln1g = (const float*)d_in[4];
    const float* ln1b = (const float*)d_in[5];
    const float* wqkv = (const float*)d_in[6];
    const float* wo   = (const float*)d_in[7];
    const float* bo   = (const float*)d_in[8];
    const float* ln2g = (const float*)d_in[9];
    const float* ln2b = (const float*)d_in[10];
    const float* wfc1 = (const float*)d_in[11];
    const float* bfc1 = (const float*)d_in[12];
    const float* wfc2 = (const float*)d_in[13];
    const float* bfc2 = (const float*)d_in[14];
    // d_in[15]=H(14), d_in[16]=W(14): fixed by problem setup, hardcoded.
    float* out = (float*)d_out;

    float *gh, *gx, *ghn, *gqkv, *gatt, *gffn;
    cudaGetSymbolAddress((void**)&gh,   g_h);
    cudaGetSymbolAddress((void**)&gx,   g_x);
    cudaGetSymbolAddress((void**)&ghn,  g_hn);
    cudaGetSymbolAddress((void**)&gqkv, g_qkv);
    cudaGetSymbolAddress((void**)&gatt, g_att);
    cudaGetSymbolAddress((void**)&gffn, g_ffn);

    const int attn_smem = (LL * 65 * 2 + 8 * LL + 8 * 64) * (int)sizeof(float); // 90368
    cudaFuncSetAttribute(attn_k, cudaFuncAttributeMaxDynamicSharedMemorySize, attn_smem);

    // 1) h = relu(box @ w1)
    embed_h_k<<<(NTOK * 384 + 255) / 256, 256>>>(box, w1);

    // 2) x = relu(h @ w2) + cat[l]
    gemm_k<1, 0, 2><<<dim3(DD / BN, NTOK / BM), 256>>>(gh, w2, nullptr, cat, gx, NTOK, DD, 384);

    // 3) hn = LN1(x)
    ln_k<<<NTOK, 256>>>(gx, ln1g, ln1b, ghn);

    // 4) qkv = hn @ wqkv
    gemm_k<0, 0, 0><<<dim3(3 * DD / BN, NTOK / BM), 256>>>(ghn, wqkv, nullptr, nullptr, gqkv, NTOK, 3 * DD, DD);

    // 5) attention
    attn_k<<<BB * NHH, 256, attn_smem>>>(gqkv, gatt);

    // 6) x = x + att @ wo + bo
    gemm_k<0, 1, 1><<<dim3(DD / BN, NTOK / BM), 256>>>(gatt, wo, bo, gx, gx, NTOK, DD, DD);

    // 7) hn = LN2(x)
    ln_k<<<NTOK, 256>>>(gx, ln2g, ln2b, ghn);

    // 8) ffn = gelu(hn @ wfc1 + bfc1)
    gemm_k<2, 1, 0><<<dim3(4 * DD / BN, NTOK / BM), 256>>>(ghn, wfc1, bfc1, nullptr, gffn, NTOK, 4 * DD, DD);

    // 9) x = x + ffn @ wfc2 + bfc2
    gemm_k<0, 1, 1><<<dim3(DD / BN, NTOK / BM), 256>>>(gffn, wfc2, bfc2, gx, gx, NTOK, DD, 4 * DD);

    // 10) mask scatter + temporal mean -> out
    grid_k<<<BB * 8 * GH * GW, 256>>>(box, out);
}

// round 3
// speedup vs baseline: 1.7616x; 1.7616x over previous
#include <cuda_runtime.h>
#include <cuda_bf16.h>
#include <math.h>
#include <stdint.h>

#define BB   16
#define TT   16
#define OO   10
#define LL   160      // T*O
#define DD   768
#define NHH  12
#define DHH  64
#define GH   14
#define GW   14
#define NTOK (BB*LL)  // 2560

// ---------------- scratch (device globals; no runtime alloc allowed) --------
__device__ float g_x  [NTOK*DD];       // residual stream, fp32
__device__ float g_qkv[NTOK*3*DD];     // fp32, read by attention

// split-bf16 activation buffers (hi + lo)
__device__ __nv_bfloat16 g_h_hi  [NTOK*384];
__device__ __nv_bfloat16 g_h_lo  [NTOK*384];
__device__ __nv_bfloat16 g_hn_hi [NTOK*DD];
__device__ __nv_bfloat16 g_hn_lo [NTOK*DD];
__device__ __nv_bfloat16 g_att_hi[NTOK*DD];
__device__ __nv_bfloat16 g_att_lo[NTOK*DD];
__device__ __nv_bfloat16 g_ffn_hi[NTOK*4*DD];
__device__ __nv_bfloat16 g_ffn_lo[NTOK*4*DD];

// transposed+split weights [N][K]
__device__ __nv_bfloat16 g_w2h  [DD*384];
__device__ __nv_bfloat16 g_w2l  [DD*384];
__device__ __nv_bfloat16 g_qkvh [3*DD*DD];
__device__ __nv_bfloat16 g_qkvl [3*DD*DD];
__device__ __nv_bfloat16 g_woh  [DD*DD];
__device__ __nv_bfloat16 g_wol  [DD*DD];
__device__ __nv_bfloat16 g_fc1h [4*DD*DD];
__device__ __nv_bfloat16 g_fc1l [4*DD*DD];
__device__ __nv_bfloat16 g_fc2h [DD*4*DD];
__device__ __nv_bfloat16 g_fc2l [DD*4*DD];

// ============================ helpers ========================================
__device__ __forceinline__ uint32_t smem_u32(const void* p) {
    uint32_t a;
    asm("{ .reg .u64 t; cvta.to.shared.u64 t, %1; cvt.u32.u64 %0, t; }" : "=r"(a) : "l"(p));
    return a;
}

__device__ __forceinline__ void split_bf16(float v, __nv_bfloat16& h, __nv_bfloat16& l) {
    h = __float2bfloat16(v);
    l = __float2bfloat16(v - __bfloat162float(h));
}

__device__ __forceinline__ void ldsm4(uint32_t* r, uint32_t addr) {
    asm volatile("ldmatrix.sync.aligned.m8n8.x4.shared.b16 {%0,%1,%2,%3}, [%4];"
        : "=r"(r[0]), "=r"(r[1]), "=r"(r[2]), "=r"(r[3]) : "r"(addr));
}

__device__ __forceinline__ void mma16816(float* c, const uint32_t* a, uint32_t b0, uint32_t b1) {
    asm volatile(
        "mma.sync.aligned.m16n8k16.row.col.f32.bf16.bf16.f32 "
        "{%0,%1,%2,%3}, {%4,%5,%6,%7}, {%8,%9}, {%0,%1,%2,%3};"
        : "+f"(c[0]), "+f"(c[1]), "+f"(c[2]), "+f"(c[3])
        : "r"(a[0]), "r"(a[1]), "r"(a[2]), "r"(a[3]), "r"(b0), "r"(b1));
}

// ---------------- weight transpose + split: W[K][N] -> Th/Tl[N][K] ----------
__global__ void tsplit_k(const float* __restrict__ W, __nv_bfloat16* __restrict__ Th,
                         __nv_bfloat16* __restrict__ Tl, int K, int N)
{
    __shared__ float t[32][33];
    int kb = blockIdx.y * 32, nb = blockIdx.x * 32;
    int x = threadIdx.x, y = threadIdx.y;   // (32, 8)
#pragma unroll
    for (int i = 0; i < 32; i += 8)
        t[y + i][x] = W[(size_t)(kb + y + i) * N + nb + x];
    __syncthreads();
#pragma unroll
    for (int i = 0; i < 32; i += 8) {
        float v = t[x][y + i];
        __nv_bfloat16 h, l; split_bf16(v, h, l);
        size_t o = (size_t)(nb + y + i) * K + kb + x;
        Th[o] = h; Tl[o] = l;
    }
}

// ---------------- embed stage 1: h = relu(box @ w1), K=4 --------------------
__global__ void embed_h_k(const float* __restrict__ box, const float* __restrict__ w1)
{
    int idx = blockIdx.x * blockDim.x + threadIdx.x;
    if (idx >= NTOK * 384) return;
    int m = idx / 384, j = idx - m * 384;
    const float* bx = box + m * 4;
    float acc = bx[0] * w1[j] + bx[1] * w1[384 + j] + bx[2] * w1[768 + j] + bx[3] * w1[1152 + j];
    acc = fmaxf(acc, 0.0f);
    split_bf16(acc, g_h_hi[idx], g_h_lo[idx]);
}

// ================= HMMA bf16 3-split GEMM ====================================
// C[M,N] = epi(A @ B^T). A hi/lo [M][K] bf16, B hi/lo [N][K] bf16.
// CTA tile 128x128, 8 warps (2m x 4n), warp tile 64x32, k-chunk 32.
// EPI: 0 plain fp32; 1 relu + res[(m%LL)*N+n]; 2 +bias+res[m*N+n]; 3 +bias, gelu -> split bf16
#define ASTR 40   // padded smem row stride in bf16 elements (80B; conflict-free ldmatrix)

template<int EPI>
__global__ void __launch_bounds__(256)
hgemm_k(const __nv_bfloat16* __restrict__ Ahi, const __nv_bfloat16* __restrict__ Alo,
        const __nv_bfloat16* __restrict__ Bhi, const __nv_bfloat16* __restrict__ Blo,
        const float* __restrict__ bias, const float* __restrict__ res,
        float* __restrict__ Cf, __nv_bfloat16* __restrict__ Chi, __nv_bfloat16* __restrict__ Clo,
        int M, int N, int K)
{
    __shared__ __align__(16) __nv_bfloat16 sAh[128 * ASTR];
    __shared__ __align__(16) __nv_bfloat16 sAl[128 * ASTR];
    __shared__ __align__(16) __nv_bfloat16 sBh[128 * ASTR];
    __shared__ __align__(16) __nv_bfloat16 sBl[128 * ASTR];

    const int tid = threadIdx.x;
    const int wid = tid >> 5, lane = tid & 31;
    const int wm = wid >> 2, wn = wid & 3;          // 2 x 4 warp grid
    const int m0 = blockIdx.y * 128, n0 = blockIdx.x * 128;

    // loader mapping: 512 segments of 16B per matrix; thread handles idx = tid + i*256
    int lrow[2], lseg[2];
#pragma unroll
    for (int i = 0; i < 2; i++) { int idx = tid + i * 256; lrow[i] = idx >> 2; lseg[i] = idx & 3; }

    float c[4][4][4] = {};

    uint4 ra_h[2], ra_l[2], rb_h[2], rb_l[2];
    const int nch = K >> 5;

    // prefetch chunk 0
#pragma unroll
    for (int i = 0; i < 2; i++) {
        size_t ao = (size_t)(m0 + lrow[i]) * K + lseg[i] * 8;
        size_t bo = (size_t)(n0 + lrow[i]) * K + lseg[i] * 8;
        ra_h[i] = *(const uint4*)(Ahi + ao);
        ra_l[i] = *(const uint4*)(Alo + ao);
        rb_h[i] = *(const uint4*)(Bhi + bo);
        rb_l[i] = *(const uint4*)(Blo + bo);
    }

    const uint32_t sAh_b = smem_u32(sAh), sAl_b = smem_u32(sAl);
    const uint32_t sBh_b = smem_u32(sBh), sBl_b = smem_u32(sBl);
    // ldmatrix lane-dependent offsets (bytes)
    const uint32_t a_lo = ((uint32_t)(lane & 15)) * (ASTR * 2) + ((uint32_t)(lane >> 4)) * 16;
    const uint32_t a_wb = (uint32_t)(wm * 64) * (ASTR * 2);
    const uint32_t b_wb = (uint32_t)(wn * 32) * (ASTR * 2);

    for (int ch = 0; ch < nch; ch++) {
        // store staged regs -> smem
#pragma unroll
        for (int i = 0; i < 2; i++) {
            int so = lrow[i] * ASTR + lseg[i] * 8;
            *(uint4*)(sAh + so) = ra_h[i];
            *(uint4*)(sAl + so) = ra_l[i];
            *(uint4*)(sBh + so) = rb_h[i];
            *(uint4*)(sBl + so) = rb_l[i];
        }
        __syncthreads();

        // prefetch next chunk
        if (ch + 1 < nch) {
            int kb = (ch + 1) << 5;
#pragma unroll
            for (int i = 0; i < 2; i++) {
                size_t ao = (size_t)(m0 + lrow[i]) * K + kb + lseg[i] * 8;
                size_t bo = (size_t)(n0 + lrow[i]) * K + kb + lseg[i] * 8;
                ra_h[i] = *(const uint4*)(Ahi + ao);
                ra_l[i] = *(const uint4*)(Alo + ao);
                rb_h[i] = *(const uint4*)(Bhi + bo);
                rb_l[i] = *(const uint4*)(Blo + bo);
            }
        }

        // two k16 steps
#pragma unroll
        for (int ks = 0; ks < 2; ks++) {
            uint32_t koff = ks * 32;   // 16 bf16 = 32 bytes
            uint32_t ah[4][4], al[4][4], bh[2][4], bl[2][4];
#pragma unroll
            for (int mt = 0; mt < 4; mt++) {
                uint32_t off = a_wb + (uint32_t)(mt * 16) * (ASTR * 2) + a_lo + koff;
                ldsm4(ah[mt], sAh_b + off);
                ldsm4(al[mt], sAl_b + off);
            }
#pragma unroll
            for (int p = 0; p < 2; p++) {
                uint32_t off = b_wb + (uint32_t)(p * 16) * (ASTR * 2) + a_lo + koff;
                ldsm4(bh[p], sBh_b + off);
                ldsm4(bl[p], sBl_b + off);
            }
#pragma unroll
            for (int mt = 0; mt < 4; mt++) {
#pragma unroll
                for (int p = 0; p < 2; p++) {
#pragma unroll
                    for (int s = 0; s < 2; s++) {
                        int nt = p * 2 + s;
                        uint32_t bh0 = bh[p][s], bh1 = bh[p][s + 2];
                        uint32_t bl0 = bl[p][s], bl1 = bl[p][s + 2];
                        mma16816(c[mt][nt], ah[mt], bh0, bh1);
                        mma16816(c[mt][nt], al[mt], bh0, bh1);
                        mma16816(c[mt][nt], ah[mt], bl0, bl1);
                    }
                }
            }
        }
        __syncthreads();
    }

    // -------- epilogue: direct register -> gmem ------------------------------
    const int rbase = m0 + wm * 64 + (lane >> 2);
    const int cbase = n0 + wn * 32 + (lane & 3) * 2;
#pragma unroll
    for (int mt = 0; mt < 4; mt++) {
#pragma unroll
        for (int rr = 0; rr < 2; rr++) {
            int m = rbase + mt * 16 + rr * 8;
#pragma unroll
            for (int nt = 0; nt < 4; nt++) {
                int n = cbase + nt * 8;
                float v0 = c[mt][nt][rr * 2 + 0];
                float v1 = c[mt][nt][rr * 2 + 1];
                if (EPI == 1) {
                    const float* rp = res + (size_t)(m % LL) * N + n;
                    v0 = fmaxf(v0, 0.0f) + rp[0];
                    v1 = fmaxf(v1, 0.0f) + rp[1];
                    *(float2*)(Cf + (size_t)m * N + n) = make_float2(v0, v1);
                } else if (EPI == 2) {
                    const float* rp = res + (size_t)m * N + n;
                    v0 += bias[n] + rp[0];
                    v1 += bias[n + 1] + rp[1];
                    *(float2*)(Cf + (size_t)m * N + n) = make_float2(v0, v1);
                } else if (EPI == 3) {
                    v0 += bias[n];
                    v1 += bias[n + 1];
                    v0 = 0.5f * v0 * (1.0f + erff(v0 * 0.70710678118654752f));
                    v1 = 0.5f * v1 * (1.0f + erff(v1 * 0.70710678118654752f));
                    __nv_bfloat16 h0, l0, h1, l1;
                    split_bf16(v0, h0, l0);
                    split_bf16(v1, h1, l1);
                    __nv_bfloat162 hp; hp.x = h0; hp.y = h1;
                    __nv_bfloat162 lp; lp.x = l0; lp.y = l1;
                    *(__nv_bfloat162*)(Chi + (size_t)m * N + n) = hp;
                    *(__nv_bfloat162*)(Clo + (size_t)m * N + n) = lp;
                } else {
                    *(float2*)(Cf + (size_t)m * N + n) = make_float2(v0, v1);
                }
            }
        }
    }
}

// ---------------- layernorm: one block per row, split-bf16 output -----------
__global__ void ln_k(const float* __restrict__ X, const float* __restrict__ g,
                     const float* __restrict__ b,
                     __nv_bfloat16* __restrict__ Yhi, __nv_bfloat16* __restrict__ Ylo)
{
    int row = blockIdx.x;
    const float* x = X + (size_t)row * DD;
    int tid = threadIdx.x;
    float v[3];
    float s = 0.f, sq = 0.f;
#pragma unroll
    for (int r = 0; r < 3; r++) {
        v[r] = x[tid + r * 256];
        s += v[r];
        sq += v[r] * v[r];
    }
    __shared__ float red0[8], red1[8];
#pragma unroll
    for (int off = 16; off; off >>= 1) {
        s += __shfl_down_sync(0xffffffffu, s, off);
        sq += __shfl_down_sync(0xffffffffu, sq, off);
    }
    if ((tid & 31) == 0) { red0[tid >> 5] = s; red1[tid >> 5] = sq; }
    __syncthreads();
    s = 0.f; sq = 0.f;
#pragma unroll
    for (int i = 0; i < 8; i++) { s += red0[i]; sq += red1[i]; }
    float mean = s * (1.0f / DD);
    float var = sq * (1.0f / DD) - mean * mean;
    float rstd = rsqrtf(var + 1e-5f);
#pragma unroll
    for (int r = 0; r < 3; r++) {
        int c = tid + r * 256;
        float y = (v[r] - mean) * rstd * g[c] + b[c];
        split_bf16(y, Yhi[(size_t)row * DD + c], Ylo[(size_t)row * DD + c]);
    }
}

// ---------------- attention: one block per (b,h), 256 threads ---------------
__global__ void attn_k(const float* __restrict__ qkv,
                       __nv_bfloat16* __restrict__ Yhi, __nv_bfloat16* __restrict__ Ylo)
{
    extern __shared__ float sm[];
    float* Ks = sm;
    float* Vs = Ks + LL * 65;
    float* Ps = Vs + LL * 65;
    float* Qs = Ps + 8 * LL;

    int bh = blockIdx.x;
    int b = bh / NHH, h = bh - b * NHH;
    int tid = threadIdx.x;

    for (int idx = tid; idx < LL * DHH; idx += 256) {
        int j = idx >> 6, d = idx & 63;
        size_t base = (size_t)(b * LL + j) * 2304 + h * 64 + d;
        Ks[j * 65 + d] = qkv[base + 768];
        Vs[j * 65 + d] = qkv[base + 1536];
    }
    __syncthreads();

    int w = tid >> 5, ln = tid & 31;
    float* ps = Ps + w * LL;
    float* qs = Qs + w * 64;

    for (int r = w; r < LL; r += 8) {
        size_t qb = (size_t)(b * LL + r) * 2304 + h * 64;
        qs[ln]      = qkv[qb + ln];
        qs[ln + 32] = qkv[qb + ln + 32];
        __syncwarp();
        float sc[5];
#pragma unroll
        for (int k5 = 0; k5 < 5; k5++) {
            int j = ln + k5 * 32;
            float a = 0.f;
#pragma unroll 8
            for (int d = 0; d < 64; d++) a = fmaf(qs[d], Ks[j * 65 + d], a);
            sc[k5] = a * 0.125f;
        }
        float mx = sc[0];
#pragma unroll
        for (int k5 = 1; k5 < 5; k5++) mx = fmaxf(mx, sc[k5]);
#pragma unroll
        for (int off = 16; off; off >>= 1) mx = fmaxf(mx, __shfl_xor_sync(0xffffffffu, mx, off));
        float sum = 0.f;
#pragma unroll
        for (int k5 = 0; k5 < 5; k5++) { sc[k5] = __expf(sc[k5] - mx); sum += sc[k5]; }
#pragma unroll
        for (int off = 16; off; off >>= 1) sum += __shfl_xor_sync(0xffffffffu, sum, off);
        float inv = 1.0f / sum;
#pragma unroll
        for (int k5 = 0; k5 < 5; k5++) ps[ln + k5 * 32] = sc[k5] * inv;
        __syncwarp();
        float o0 = 0.f, o1 = 0.f;
#pragma unroll 8
        for (int j = 0; j < LL; j++) {
            float p = ps[j];
            o0 = fmaf(p, Vs[j * 65 + ln], o0);
            o1 = fmaf(p, Vs[j * 65 + ln + 32], o1);
        }
        size_t ob = (size_t)(b * LL + r) * DD + h * 64;
        split_bf16(o0, Yhi[ob + ln], Ylo[ob + ln]);
        split_bf16(o1, Yhi[ob + ln + 32], Ylo[ob + ln + 32]);
        __syncwarp();
    }
}

// ---------------- box-mask scatter + temporal mean ---------------------------
__global__ void grid_k(const float* __restrict__ box, float* __restrict__ out)
{
    int blk = blockIdx.x;
    int w = blk % GW;
    int hh = (blk / GW) % GH;
    int tg = (blk / (GW * GH)) & 7;
    int b = blk / (GW * GH * 8);
    int tid = threadIdx.x;

    __shared__ float flg[20];
    if (tid < 20) {
        int t = tg * 2 + tid / 10;
        int o = tid % 10;
        const float* bx = box + (size_t)((b * TT + t) * OO + o) * 4;
        float x1 = fminf(bx[0], bx[2]), x2 = fmaxf(bx[0], bx[2]);
        float y1 = fminf(bx[1], bx[3]), y2 = fmaxf(bx[1], bx[3]);
        float cy = (hh + 0.5f) / 14.0f;
        float cx = (w + 0.5f) / 14.0f;
        flg[tid] = (cy >= y1 && cy <= y2 && cx >= x1 && cx <= x2) ? 1.0f : 0.0f;
    }
    __syncthreads();

    float a0 = 0.f, a1 = 0.f, a2 = 0.f;
#pragma unroll
    for (int e = 0; e < 20; e++) {
        if (flg[e] > 0.f) {
            const float* f = g_x + (size_t)(b * LL + (tg * 2 + e / 10) * OO + (e % 10)) * DD + tid;
            a0 += f[0];
            a1 += f[256];
            a2 += f[512];
        }
    }
    size_t ob = (size_t)blk * DD + tid;
    out[ob]       = 0.5f * a0;
    out[ob + 256] = 0.5f * a1;
    out[ob + 512] = 0.5f * a2;
}

// ---------------- launch ------------------------------------------------------
extern "C" void kernel_launch(void* const* d_in, const int* in_sizes, int n_in,
                              void* d_out, int out_size)
{
    const float* box  = (const float*)d_in[0];
    const float* cat  = (const float*)d_in[1];
    const float* w1   = (const float*)d_in[2];
    const float* w2   = (const float*)d_in[3];
    const float* ln1g = (const float*)d_in[4];
    const float* ln1b = (const float*)d_in[5];
    const float* wqkv = (const float*)d_in[6];
    const float* wo   = (const float*)d_in[7];
    const float* bo   = (const float*)d_in[8];
    const float* ln2g = (const float*)d_in[9];
    const float* ln2b = (const float*)d_in[10];
    const float* wfc1 = (const float*)d_in[11];
    const float* bfc1 = (const float*)d_in[12];
    const float* wfc2 = (const float*)d_in[13];
    const float* bfc2 = (const float*)d_in[14];
    float* out = (float*)d_out;

    float *gx, *gqkv;
    __nv_bfloat16 *ghh, *ghl, *ghnh, *ghnl, *gatth, *gattl, *gffnh, *gffnl;
    __nv_bfloat16 *w2h, *w2l, *qkh, *qkl, *woh, *wol, *f1h, *f1l, *f2h, *f2l;
    cudaGetSymbolAddress((void**)&gx,    g_x);
    cudaGetSymbolAddress((void**)&gqkv,  g_qkv);
    cudaGetSymbolAddress((void**)&ghh,   g_h_hi);
    cudaGetSymbolAddress((void**)&ghl,   g_h_lo);
    cudaGetSymbolAddress((void**)&ghnh,  g_hn_hi);
    cudaGetSymbolAddress((void**)&ghnl,  g_hn_lo);
    cudaGetSymbolAddress((void**)&gatth, g_att_hi);
    cudaGetSymbolAddress((void**)&gattl, g_att_lo);
    cudaGetSymbolAddress((void**)&gffnh, g_ffn_hi);
    cudaGetSymbolAddress((void**)&gffnl, g_ffn_lo);
    cudaGetSymbolAddress((void**)&w2h,   g_w2h);
    cudaGetSymbolAddress((void**)&w2l,   g_w2l);
    cudaGetSymbolAddress((void**)&qkh,   g_qkvh);
    cudaGetSymbolAddress((void**)&qkl,   g_qkvl);
    cudaGetSymbolAddress((void**)&woh,   g_woh);
    cudaGetSymbolAddress((void**)&wol,   g_wol);
    cudaGetSymbolAddress((void**)&f1h,   g_fc1h);
    cudaGetSymbolAddress((void**)&f1l,   g_fc1l);
    cudaGetSymbolAddress((void**)&f2h,   g_fc2h);
    cudaGetSymbolAddress((void**)&f2l,   g_fc2l);

    const int attn_smem = (LL * 65 * 2 + 8 * LL + 8 * 64) * (int)sizeof(float);
    cudaFuncSetAttribute(attn_k, cudaFuncAttributeMaxDynamicSharedMemorySize, attn_smem);

    dim3 tb(32, 8);
    // weight transpose+split (weights are inputs; must be done every launch)
    tsplit_k<<<dim3(DD / 32, 384 / 32), tb>>>(w2,   w2h, w2l, 384, DD);
    tsplit_k<<<dim3(3 * DD / 32, DD / 32), tb>>>(wqkv, qkh, qkl, DD, 3 * DD);
    tsplit_k<<<dim3(DD / 32, DD / 32), tb>>>(wo,   woh, wol, DD, DD);
    tsplit_k<<<dim3(4 * DD / 32, DD / 32), tb>>>(wfc1, f1h, f1l, DD, 4 * DD);
    tsplit_k<<<dim3(DD / 32, 4 * DD / 32), tb>>>(wfc2, f2h, f2l, 4 * DD, DD);

    // 1) h = relu(box @ w1)
    embed_h_k<<<(NTOK * 384 + 255) / 256, 256>>>(box, w1);

    // 2) x = relu(h @ w2) + cat
    hgemm_k<1><<<dim3(DD / 128, NTOK / 128), 256>>>(
        ghh, ghl, w2h, w2l, nullptr, cat, gx, nullptr, nullptr, NTOK, DD, 384);

    // 3) hn = LN1(x)
    ln_k<<<NTOK, 256>>>(gx, ln1g, ln1b, ghnh, ghnl);

    // 4) qkv = hn @ wqkv
    hgemm_k<0><<<dim3(3 * DD / 128, NTOK / 128), 256>>>(
        ghnh, ghnl, qkh, qkl, nullptr, nullptr, gqkv, nullptr, nullptr, NTOK, 3 * DD, DD);

    // 5) attention
    attn_k<<<BB * NHH, 256, attn_smem>>>(gqkv, gatth, gattl);

    // 6) x = x + att @ wo + bo
    hgemm_k<2><<<dim3(DD / 128, NTOK / 128), 256>>>(
        gatth, gattl, woh, wol, bo, gx, gx, nullptr, nullptr, NTOK, DD, DD);

    // 7) hn = LN2(x)
    ln_k<<<NTOK, 256>>>(gx, ln2g, ln2b, ghnh, ghnl);

    // 8) ffn = gelu(hn @ wfc1 + bfc1) -> split bf16
    hgemm_k<3><<<dim3(4 * DD / 128, NTOK / 128), 256>>>(
        ghnh, ghnl, f1h, f1l, bfc1, nullptr, nullptr, gffnh, gffnl, NTOK, 4 * DD, DD);

    // 9) x = x + ffn @ wfc2 + bfc2
    hgemm_k<2><<<dim3(DD / 128, NTOK / 128), 256>>>(
        gffnh, gffnl, f2h, f2l, bfc2, gx, gx, nullptr, nullptr, NTOK, DD, 4 * DD);

    // 10) mask scatter + temporal mean -> out
    grid_k<<<BB * 8 * GH * GW, 256>>>(box, out);
}

// round 4
// speedup vs baseline: 1.8286x; 1.0380x over previous
#include <cuda_runtime.h>
#include <cuda_bf16.h>
#include <math.h>
#include <stdint.h>

#define BB   16
#define TT   16
#define OO   10
#define LL   160      // T*O
#define DD   768
#define NHH  12
#define DHH  64
#define GH   14
#define GW   14
#define NTOK (BB*LL)  // 2560

// ---------------- scratch (device globals; no runtime alloc allowed) --------
__device__ float g_x  [NTOK*DD];       // residual stream, fp32
__device__ float g_qkv[NTOK*3*DD];     // fp32, read by attention

__device__ __nv_bfloat16 g_h_hi  [NTOK*384];
__device__ __nv_bfloat16 g_h_lo  [NTOK*384];
__device__ __nv_bfloat16 g_hn_hi [NTOK*DD];
__device__ __nv_bfloat16 g_hn_lo [NTOK*DD];
__device__ __nv_bfloat16 g_att_hi[NTOK*DD];
__device__ __nv_bfloat16 g_att_lo[NTOK*DD];
__device__ __nv_bfloat16 g_ffn_hi[NTOK*4*DD];
__device__ __nv_bfloat16 g_ffn_lo[NTOK*4*DD];

// transposed+split weights [N][K]
__device__ __nv_bfloat16 g_w2h  [DD*384];
__device__ __nv_bfloat16 g_w2l  [DD*384];
__device__ __nv_bfloat16 g_qkvh [3*DD*DD];
__device__ __nv_bfloat16 g_qkvl [3*DD*DD];
__device__ __nv_bfloat16 g_woh  [DD*DD];
__device__ __nv_bfloat16 g_wol  [DD*DD];
__device__ __nv_bfloat16 g_fc1h [4*DD*DD];
__device__ __nv_bfloat16 g_fc1l [4*DD*DD];
__device__ __nv_bfloat16 g_fc2h [DD*4*DD];
__device__ __nv_bfloat16 g_fc2l [DD*4*DD];

// ============================ helpers ========================================
__device__ __forceinline__ uint32_t smem_u32(const void* p) {
    uint32_t a;
    asm("{ .reg .u64 t; cvta.to.shared.u64 t, %1; cvt.u32.u64 %0, t; }" : "=r"(a) : "l"(p));
    return a;
}
__device__ __forceinline__ void split_bf16(float v, __nv_bfloat16& h, __nv_bfloat16& l) {
    h = __float2bfloat16(v);
    l = __float2bfloat16(v - __bfloat162float(h));
}
__device__ __forceinline__ void ldsm4(uint32_t* r, uint32_t addr) {
    asm volatile("ldmatrix.sync.aligned.m8n8.x4.shared.b16 {%0,%1,%2,%3}, [%4];"
        : "=r"(r[0]), "=r"(r[1]), "=r"(r[2]), "=r"(r[3]) : "r"(addr));
}
__device__ __forceinline__ void mma16816(float* c, const uint32_t* a, uint32_t b0, uint32_t b1) {
    asm volatile(
        "mma.sync.aligned.m16n8k16.row.col.f32.bf16.bf16.f32 "
        "{%0,%1,%2,%3}, {%4,%5,%6,%7}, {%8,%9}, {%0,%1,%2,%3};"
        : "+f"(c[0]), "+f"(c[1]), "+f"(c[2]), "+f"(c[3])
        : "r"(a[0]), "r"(a[1]), "r"(a[2]), "r"(a[3]), "r"(b0), "r"(b1));
}
__device__ __forceinline__ void cpa16(uint32_t dst, const void* src) {
    asm volatile("cp.async.cg.shared.global [%0], [%1], 16;" :: "r"(dst), "l"(src) : "memory");
}
#define CP_COMMIT() asm volatile("cp.async.commit_group;" ::: "memory")
#define CP_WAIT0()  asm volatile("cp.async.wait_group 0;" ::: "memory")

// ---------------- fused weight transpose + split (one launch) ---------------
// W[K][N] -> Th/Tl [N][K] for all 5 weights
__global__ void tsplit_all_k(
    const float* __restrict__ w2, const float* __restrict__ wqkv,
    const float* __restrict__ wo, const float* __restrict__ wfc1,
    const float* __restrict__ wfc2)
{
    int b = blockIdx.x;
    const float* W; __nv_bfloat16 *Th, *Tl; int K, N, nbx;
    if (b < 288)       { W = w2;   Th = g_w2h;  Tl = g_w2l;  K = 384;  N = 768;  nbx = 24; }
    else if (b < 2016) { b -= 288;  W = wqkv; Th = g_qkvh; Tl = g_qkvl; K = 768;  N = 2304; nbx = 72; }
    else if (b < 2592) { b -= 2016; W = wo;   Th = g_woh;  Tl = g_wol;  K = 768;  N = 768;  nbx = 24; }
    else if (b < 4896) { b -= 2592; W = wfc1; Th = g_fc1h; Tl = g_fc1l; K = 768;  N = 3072; nbx = 96; }
    else               { b -= 4896; W = wfc2; Th = g_fc2h; Tl = g_fc2l; K = 3072; N = 768;  nbx = 24; }
    int nb = (b % nbx) * 32, kb = (b / nbx) * 32;

    __shared__ float t[32][33];
    int x = threadIdx.x, y = threadIdx.y;   // (32, 8)
#pragma unroll
    for (int i = 0; i < 32; i += 8)
        t[y + i][x] = W[(size_t)(kb + y + i) * N + nb + x];
    __syncthreads();
#pragma unroll
    for (int i = 0; i < 32; i += 8) {
        float v = t[x][y + i];
        __nv_bfloat16 h, l; split_bf16(v, h, l);
        size_t o = (size_t)(nb + y + i) * K + kb + x;
        Th[o] = h; Tl[o] = l;
    }
}

// ---------------- embed stage 1: h = relu(box @ w1), K=4 --------------------
__global__ void embed_h_k(const float* __restrict__ box, const float* __restrict__ w1)
{
    int idx = blockIdx.x * blockDim.x + threadIdx.x;
    if (idx >= NTOK * 384) return;
    int m = idx / 384, j = idx - m * 384;
    const float* bx = box + m * 4;
    float acc = bx[0] * w1[j] + bx[1] * w1[384 + j] + bx[2] * w1[768 + j] + bx[3] * w1[1152 + j];
    acc = fmaxf(acc, 0.0f);
    split_bf16(acc, g_h_hi[idx], g_h_lo[idx]);
}

// ================= HMMA bf16 3-split GEMM, cp.async double-buffered =========
// C[M,N] = epi(A @ B^T). A hi/lo [M][K] bf16, B hi/lo [N][K] bf16.
// CTA tile TM x 128 (TM = 128 or 64), 8 warps (2m x 4n), k-chunk 32.
// EPI: 0 plain fp32; 1 relu + res[(m%LL)*N+n]; 2 +bias+res[m*N+n]; 3 +bias, gelu -> split bf16
template<int EPI, int TM>
__global__ void __launch_bounds__(256)
hgemm_k(const __nv_bfloat16* __restrict__ Ahi, const __nv_bfloat16* __restrict__ Alo,
        const __nv_bfloat16* __restrict__ Bhi, const __nv_bfloat16* __restrict__ Blo,
        const float* __restrict__ bias, const float* __restrict__ res,
        float* __restrict__ Cf, __nv_bfloat16* __restrict__ Chi, __nv_bfloat16* __restrict__ Clo,
        int M, int N, int K)
{
    extern __shared__ __align__(16) __nv_bfloat16 smbuf[];
    constexpr int MT = TM / 32;                 // warp m-subtiles of 16
    constexpr uint32_t STG_B = (TM + 128) * 160;     // bytes per stage (hi+lo, A+B, 80B rows)
    const uint32_t offAh = 0;
    const uint32_t offAl = (uint32_t)TM * 80;
    const uint32_t offBh = (uint32_t)TM * 160;
    const uint32_t offBl = (uint32_t)TM * 160 + 128 * 80;

    const int tid = threadIdx.x;
    const int wid = tid >> 5, lane = tid & 31;
    const int wm = wid >> 2, wn = wid & 3;
    const int m0 = blockIdx.y * TM, n0 = blockIdx.x * 128;
    const uint32_t smb = smem_u32(smbuf);

    const int nch = K >> 5;

    auto load_stage = [&](int st, int kb) {
        uint32_t sb = smb + (uint32_t)st * STG_B;
#pragma unroll
        for (int s = tid; s < TM * 4; s += 256) {
            int row = s >> 2, seg = s & 3;
            uint32_t d = sb + (uint32_t)(row * 80 + seg * 16);
            size_t go = (size_t)(m0 + row) * K + kb + seg * 8;
            cpa16(d + offAh, Ahi + go);
            cpa16(d + offAl, Alo + go);
        }
#pragma unroll
        for (int s = tid; s < 512; s += 256) {
            int row = s >> 2, seg = s & 3;
            uint32_t d = sb + (uint32_t)(row * 80 + seg * 16);
            size_t go = (size_t)(n0 + row) * K + kb + seg * 8;
            cpa16(d + offBh, Bhi + go);
            cpa16(d + offBl, Blo + go);
        }
    };

    const uint32_t a_lo = (uint32_t)(lane & 15) * 80 + (uint32_t)(lane >> 4) * 16;
    const uint32_t a_wb = (uint32_t)(wm * (TM / 2)) * 80;
    const uint32_t b_wb = (uint32_t)(wn * 32) * 80;

    float c[MT][4][4] = {};

    load_stage(0, 0);
    CP_COMMIT();

    for (int ch = 0; ch < nch; ch++) {
        CP_WAIT0();
        __syncthreads();
        if (ch + 1 < nch) {
            load_stage((ch + 1) & 1, (ch + 1) << 5);
            CP_COMMIT();
        }
        uint32_t sb = smb + (uint32_t)(ch & 1) * STG_B;
#pragma unroll
        for (int ks = 0; ks < 2; ks++) {
            uint32_t koff = ks * 32;
            uint32_t ah[MT][4], al[MT][4], bh[2][4], bl[2][4];
#pragma unroll
            for (int mt = 0; mt < MT; mt++) {
                uint32_t off = a_wb + (uint32_t)(mt * 16) * 80 + a_lo + koff;
                ldsm4(ah[mt], sb + offAh + off);
                ldsm4(al[mt], sb + offAl + off);
            }
#pragma unroll
            for (int p = 0; p < 2; p++) {
                uint32_t off = b_wb + (uint32_t)(p * 16) * 80 + a_lo + koff;
                ldsm4(bh[p], sb + offBh + off);
                ldsm4(bl[p], sb + offBl + off);
            }
#pragma unroll
            for (int mt = 0; mt < MT; mt++) {
#pragma unroll
                for (int p = 0; p < 2; p++) {
#pragma unroll
                    for (int s = 0; s < 2; s++) {
                        int nt = p * 2 + s;
                        uint32_t bh0 = bh[p][s], bh1 = bh[p][s + 2];
                        uint32_t bl0 = bl[p][s], bl1 = bl[p][s + 2];
                        mma16816(c[mt][nt], ah[mt], bh0, bh1);
                        mma16816(c[mt][nt], al[mt], bh0, bh1);
                        mma16816(c[mt][nt], ah[mt], bl0, bl1);
                    }
                }
            }
        }
        __syncthreads();
    }

    // -------- epilogue: direct register -> gmem ------------------------------
    const int rbase = m0 + wm * (TM / 2) + (lane >> 2);
    const int cbase = n0 + wn * 32 + (lane & 3) * 2;
#pragma unroll
    for (int mt = 0; mt < MT; mt++) {
#pragma unroll
        for (int rr = 0; rr < 2; rr++) {
            int m = rbase + mt * 16 + rr * 8;
#pragma unroll
            for (int nt = 0; nt < 4; nt++) {
                int n = cbase + nt * 8;
                float v0 = c[mt][nt][rr * 2 + 0];
                float v1 = c[mt][nt][rr * 2 + 1];
                if (EPI == 1) {
                    const float* rp = res + (size_t)(m % LL) * N + n;
                    v0 = fmaxf(v0, 0.0f) + rp[0];
                    v1 = fmaxf(v1, 0.0f) + rp[1];
                    *(float2*)(Cf + (size_t)m * N + n) = make_float2(v0, v1);
                } else if (EPI == 2) {
                    const float* rp = res + (size_t)m * N + n;
                    v0 += bias[n] + rp[0];
                    v1 += bias[n + 1] + rp[1];
                    *(float2*)(Cf + (size_t)m * N + n) = make_float2(v0, v1);
                } else if (EPI == 3) {
                    v0 += bias[n];
                    v1 += bias[n + 1];
                    v0 = 0.5f * v0 * (1.0f + erff(v0 * 0.70710678118654752f));
                    v1 = 0.5f * v1 * (1.0f + erff(v1 * 0.70710678118654752f));
                    __nv_bfloat16 h0, l0, h1, l1;
                    split_bf16(v0, h0, l0);
                    split_bf16(v1, h1, l1);
                    __nv_bfloat162 hp; hp.x = h0; hp.y = h1;
                    __nv_bfloat162 lp; lp.x = l0; lp.y = l1;
                    *(__nv_bfloat162*)(Chi + (size_t)m * N + n) = hp;
                    *(__nv_bfloat162*)(Clo + (size_t)m * N + n) = lp;
                } else {
                    *(float2*)(Cf + (size_t)m * N + n) = make_float2(v0, v1);
                }
            }
        }
    }
}

// ---------------- layernorm: one block per row, split-bf16 output -----------
__global__ void ln_k(const float* __restrict__ X, const float* __restrict__ g,
                     const float* __restrict__ b,
                     __nv_bfloat16* __restrict__ Yhi, __nv_bfloat16* __restrict__ Ylo)
{
    int row = blockIdx.x;
    const float* x = X + (size_t)row * DD;
    int tid = threadIdx.x;
    float v[3];
    float s = 0.f, sq = 0.f;
#pragma unroll
    for (int r = 0; r < 3; r++) {
        v[r] = x[tid + r * 256];
        s += v[r];
        sq += v[r] * v[r];
    }
    __shared__ float red0[8], red1[8];
#pragma unroll
    for (int off = 16; off; off >>= 1) {
        s += __shfl_down_sync(0xffffffffu, s, off);
        sq += __shfl_down_sync(0xffffffffu, sq, off);
    }
    if ((tid & 31) == 0) { red0[tid >> 5] = s; red1[tid >> 5] = sq; }
    __syncthreads();
    s = 0.f; sq = 0.f;
#pragma unroll
    for (int i = 0; i < 8; i++) { s += red0[i]; sq += red1[i]; }
    float mean = s * (1.0f / DD);
    float var = sq * (1.0f / DD) - mean * mean;
    float rstd = rsqrtf(var + 1e-5f);
#pragma unroll
    for (int r = 0; r < 3; r++) {
        int c = tid + r * 256;
        float y = (v[r] - mean) * rstd * g[c] + b[c];
        split_bf16(y, Yhi[(size_t)row * DD + c], Ylo[(size_t)row * DD + c]);
    }
}

// ---------------- attention: one block per (b,h), 256 threads ---------------
__global__ void attn_k(const float* __restrict__ qkv,
                       __nv_bfloat16* __restrict__ Yhi, __nv_bfloat16* __restrict__ Ylo)
{
    extern __shared__ float sm[];
    float* Ks = sm;
    float* Vs = Ks + LL * 65;
    float* Ps = Vs + LL * 65;
    float* Qs = Ps + 8 * LL;

    int bh = blockIdx.x;
    int b = bh / NHH, h = bh - b * NHH;
    int tid = threadIdx.x;

    for (int idx = tid; idx < LL * DHH; idx += 256) {
        int j = idx >> 6, d = idx & 63;
        size_t base = (size_t)(b * LL + j) * 2304 + h * 64 + d;
        Ks[j * 65 + d] = qkv[base + 768];
        Vs[j * 65 + d] = qkv[base + 1536];
    }
    __syncthreads();

    int w = tid >> 5, ln = tid & 31;
    float* ps = Ps + w * LL;
    float* qs = Qs + w * 64;

    for (int r = w; r < LL; r += 8) {
        size_t qb = (size_t)(b * LL + r) * 2304 + h * 64;
        qs[ln]      = qkv[qb + ln];
        qs[ln + 32] = qkv[qb + ln + 32];
        __syncwarp();
        float sc[5];
#pragma unroll
        for (int k5 = 0; k5 < 5; k5++) {
            int j = ln + k5 * 32;
            float a = 0.f;
#pragma unroll 8
            for (int d = 0; d < 64; d++) a = fmaf(qs[d], Ks[j * 65 + d], a);
            sc[k5] = a * 0.125f;
        }
        float mx = sc[0];
#pragma unroll
        for (int k5 = 1; k5 < 5; k5++) mx = fmaxf(mx, sc[k5]);
#pragma unroll
        for (int off = 16; off; off >>= 1) mx = fmaxf(mx, __shfl_xor_sync(0xffffffffu, mx, off));
        float sum = 0.f;
#pragma unroll
        for (int k5 = 0; k5 < 5; k5++) { sc[k5] = __expf(sc[k5] - mx); sum += sc[k5]; }
#pragma unroll
        for (int off = 16; off; off >>= 1) sum += __shfl_xor_sync(0xffffffffu, sum, off);
        float inv = 1.0f / sum;
#pragma unroll
        for (int k5 = 0; k5 < 5; k5++) ps[ln + k5 * 32] = sc[k5] * inv;
        __syncwarp();
        float o0 = 0.f, o1 = 0.f;
#pragma unroll 8
        for (int j = 0; j < LL; j++) {
            float p = ps[j];
            o0 = fmaf(p, Vs[j * 65 + ln], o0);
            o1 = fmaf(p, Vs[j * 65 + ln + 32], o1);
        }
        size_t ob = (size_t)(b * LL + r) * DD + h * 64;
        split_bf16(o0, Yhi[ob + ln], Ylo[ob + ln]);
        split_bf16(o1, Yhi[ob + ln + 32], Ylo[ob + ln + 32]);
        __syncwarp();
    }
}

// ---------------- box-mask scatter + temporal mean ---------------------------
__global__ void grid_k(const float* __restrict__ box, float* __restrict__ out)
{
    int blk = blockIdx.x;
    int w = blk % GW;
    int hh = (blk / GW) % GH;
    int tg = (blk / (GW * GH)) & 7;
    int b = blk / (GW * GH * 8);
    int tid = threadIdx.x;

    __shared__ float flg[20];
    if (tid < 20) {
        int t = tg * 2 + tid / 10;
        int o = tid % 10;
        const float* bx = box + (size_t)((b * TT + t) * OO + o) * 4;
        float x1 = fminf(bx[0], bx[2]), x2 = fmaxf(bx[0], bx[2]);
        float y1 = fminf(bx[1], bx[3]), y2 = fmaxf(bx[1], bx[3]);
        float cy = (hh + 0.5f) / 14.0f;
        float cx = (w + 0.5f) / 14.0f;
        flg[tid] = (cy >= y1 && cy <= y2 && cx >= x1 && cx <= x2) ? 1.0f : 0.0f;
    }
    __syncthreads();

    float a0 = 0.f, a1 = 0.f, a2 = 0.f;
#pragma unroll
    for (int e = 0; e < 20; e++) {
        if (flg[e] > 0.f) {
            const float* f = g_x + (size_t)(b * LL + (tg * 2 + e / 10) * OO + (e % 10)) * DD + tid;
            a0 += f[0];
            a1 += f[256];
            a2 += f[512];
        }
    }
    size_t ob = (size_t)blk * DD + tid;
    out[ob]       = 0.5f * a0;
    out[ob + 256] = 0.5f * a1;
    out[ob + 512] = 0.5f * a2;
}

// ---------------- launch ------------------------------------------------------
extern "C" void kernel_launch(void* const* d_in, const int* in_sizes, int n_in,
                              void* d_out, int out_size)
{
    const float* box  = (const float*)d_in[0];
    const float* cat  = (const float*)d_in[1];
    const float* w1   = (const float*)d_in[2];
    const float* w2   = (const float*)d_in[3];
    const float* ln1g = (const float*)d_in[4];
    const float* ln1b = (const float*)d_in[5];
    const float* wqkv = (const float*)d_in[6];
    const float* wo   = (const float*)d_in[7];
    const float* bo   = (const float*)d_in[8];
    const float* ln2g = (const float*)d_in[9];
    const float* ln2b = (const float*)d_in[10];
    const float* wfc1 = (const float*)d_in[11];
    const float* bfc1 = (const float*)d_in[12];
    const float* wfc2 = (const float*)d_in[13];
    const float* bfc2 = (const float*)d_in[14];
    float* out = (float*)d_out;

    float *gx, *gqkv;
    __nv_bfloat16 *ghh, *ghl, *ghnh, *ghnl, *gatth, *gattl, *gffnh, *gffnl;
    __nv_bfloat16 *w2h, *w2l, *qkh, *qkl, *woh, *wol, *f1h, *f1l, *f2h, *f2l;
    cudaGetSymbolAddress((void**)&gx,    g_x);
    cudaGetSymbolAddress((void**)&gqkv,  g_qkv);
    cudaGetSymbolAddress((void**)&ghh,   g_h_hi);
    cudaGetSymbolAddress((void**)&ghl,   g_h_lo);
    cudaGetSymbolAddress((void**)&ghnh,  g_hn_hi);
    cudaGetSymbolAddress((void**)&ghnl,  g_hn_lo);
    cudaGetSymbolAddress((void**)&gatth, g_att_hi);
    cudaGetSymbolAddress((void**)&gattl, g_att_lo);
    cudaGetSymbolAddress((void**)&gffnh, g_ffn_hi);
    cudaGetSymbolAddress((void**)&gffnl, g_ffn_lo);
    cudaGetSymbolAddress((void**)&w2h,   g_w2h);
    cudaGetSymbolAddress((void**)&w2l,   g_w2l);
    cudaGetSymbolAddress((void**)&qkh,   g_qkvh);
    cudaGetSymbolAddress((void**)&qkl,   g_qkvl);
    cudaGetSymbolAddress((void**)&woh,   g_woh);
    cudaGetSymbolAddress((void**)&wol,   g_wol);
    cudaGetSymbolAddress((void**)&f1h,   g_fc1h);
    cudaGetSymbolAddress((void**)&f1l,   g_fc1l);
    cudaGetSymbolAddress((void**)&f2h,   g_fc2h);
    cudaGetSymbolAddress((void**)&f2l,   g_fc2l);

    const int attn_smem = (LL * 65 * 2 + 8 * LL + 8 * 64) * (int)sizeof(float);
    cudaFuncSetAttribute(attn_k, cudaFuncAttributeMaxDynamicSharedMemorySize, attn_smem);

    const int smem128 = (128 + 128) * 160 * 2;  // 81920
    const int smem64  = (64 + 128) * 160 * 2;   // 61440
    cudaFuncSetAttribute(hgemm_k<0, 128>, cudaFuncAttributeMaxDynamicSharedMemorySize, smem128);
    cudaFuncSetAttribute(hgemm_k<3, 128>, cudaFuncAttributeMaxDynamicSharedMemorySize, smem128);
    cudaFuncSetAttribute(hgemm_k<1, 64>,  cudaFuncAttributeMaxDynamicSharedMemorySize, smem64);
    cudaFuncSetAttribute(hgemm_k<2, 64>,  cudaFuncAttributeMaxDynamicSharedMemorySize, smem64);

    // weight transpose+split: single fused launch
    tsplit_all_k<<<7200, dim3(32, 8)>>>(w2, wqkv, wo, wfc1, wfc2);

    // 1) h = relu(box @ w1)
    embed_h_k<<<(NTOK * 384 + 255) / 256, 256>>>(box, w1);

    // 2) x = relu(h @ w2) + cat
    hgemm_k<1, 64><<<dim3(DD / 128, NTOK / 64), 256, smem64>>>(
        ghh, ghl, w2h, w2l, nullptr, cat, gx, nullptr, nullptr, NTOK, DD, 384);

    // 3) hn = LN1(x)
    ln_k<<<NTOK, 256>>>(gx, ln1g, ln1b, ghnh, ghnl);

    // 4) qkv = hn @ wqkv
    hgemm_k<0, 128><<<dim3(3 * DD / 128, NTOK / 128), 256, smem128>>>(
        ghnh, ghnl, qkh, qkl, nullptr, nullptr, gqkv, nullptr, nullptr, NTOK, 3 * DD, DD);

    // 5) attention
    attn_k<<<BB * NHH, 256, attn_smem>>>(gqkv, gatth, gattl);

    // 6) x = x + att @ wo + bo
    hgemm_k<2, 64><<<dim3(DD / 128, NTOK / 64), 256, smem64>>>(
        gatth, gattl, woh, wol, bo, gx, gx, nullptr, nullptr, NTOK, DD, DD);

    // 7) hn = LN2(x)
    ln_k<<<NTOK, 256>>>(gx, ln2g, ln2b, ghnh, ghnl);

    // 8) ffn = gelu(hn @ wfc1 + bfc1) -> split bf16
    hgemm_k<3, 128><<<dim3(4 * DD / 128, NTOK / 128), 256, smem128>>>(
        ghnh, ghnl, f1h, f1l, bfc1, nullptr, nullptr, gffnh, gffnl, NTOK, 4 * DD, DD);

    // 9) x = x + ffn @ wfc2 + bfc2
    hgemm_k<2, 64><<<dim3(DD / 128, NTOK / 64), 256, smem64>>>(
        gffnh, gffnl, f2h, f2l, bfc2, gx, gx, nullptr, nullptr, NTOK, DD, 4 * DD);

    // 10) mask scatter + temporal mean -> out
    grid_k<<<BB * 8 * GH * GW, 256>>>(box, out);
}

// round 5
// speedup vs baseline: 2.2980x; 1.2567x over previous
#include <cuda_runtime.h>
#include <cuda_fp16.h>
#include <math.h>
#include <stdint.h>

#define BB   16
#define TT   16
#define OO   10
#define LL   160      // T*O
#define DD   768
#define NHH  12
#define DHH  64
#define GH   14
#define GW   14
#define NTOK (BB*LL)  // 2560

// ---------------- scratch (device globals; no runtime alloc allowed) --------
__device__ float g_x  [NTOK*DD];       // residual stream, fp32
__device__ float g_qkv[NTOK*3*DD];     // fp32, read by attention

// split-fp16 activation buffers (hi + lo)
__device__ __half g_h_hi  [NTOK*384];
__device__ __half g_h_lo  [NTOK*384];
__device__ __half g_hn_hi [NTOK*DD];
__device__ __half g_hn_lo [NTOK*DD];
__device__ __half g_att_hi[NTOK*DD];
__device__ __half g_att_lo[NTOK*DD];
__device__ __half g_ffn_hi[NTOK*4*DD];
__device__ __half g_ffn_lo[NTOK*4*DD];

// transposed weights [N][K], single fp16 (round-to-nearest)
__device__ __half g_w2h  [DD*384];
__device__ __half g_qkvh [3*DD*DD];
__device__ __half g_woh  [DD*DD];
__device__ __half g_fc1h [4*DD*DD];
__device__ __half g_fc2h [DD*4*DD];

// ============================ helpers ========================================
__device__ __forceinline__ uint32_t smem_u32(const void* p) {
    uint32_t a;
    asm("{ .reg .u64 t; cvta.to.shared.u64 t, %1; cvt.u32.u64 %0, t; }" : "=r"(a) : "l"(p));
    return a;
}
__device__ __forceinline__ void split_f16(float v, __half& h, __half& l) {
    h = __float2half_rn(v);
    l = __float2half_rn(v - __half2float(h));
}
__device__ __forceinline__ void ldsm4(uint32_t* r, uint32_t addr) {
    asm volatile("ldmatrix.sync.aligned.m8n8.x4.shared.b16 {%0,%1,%2,%3}, [%4];"
        : "=r"(r[0]), "=r"(r[1]), "=r"(r[2]), "=r"(r[3]) : "r"(addr));
}
__device__ __forceinline__ void mma16816(float* c, const uint32_t* a, uint32_t b0, uint32_t b1) {
    asm volatile(
        "mma.sync.aligned.m16n8k16.row.col.f32.f16.f16.f32 "
        "{%0,%1,%2,%3}, {%4,%5,%6,%7}, {%8,%9}, {%0,%1,%2,%3};"
        : "+f"(c[0]), "+f"(c[1]), "+f"(c[2]), "+f"(c[3])
        : "r"(a[0]), "r"(a[1]), "r"(a[2]), "r"(a[3]), "r"(b0), "r"(b1));
}
__device__ __forceinline__ void cpa16(uint32_t dst, const void* src) {
    asm volatile("cp.async.cg.shared.global [%0], [%1], 16;" :: "r"(dst), "l"(src) : "memory");
}
#define CP_COMMIT() asm volatile("cp.async.commit_group;" ::: "memory")
#define CP_WAIT0()  asm volatile("cp.async.wait_group 0;" ::: "memory")

// ---------------- fused weight transpose (one launch, fp16 RN) --------------
// W[K][N] -> Th [N][K]
__global__ void tsplit_all_k(
    const float* __restrict__ w2, const float* __restrict__ wqkv,
    const float* __restrict__ wo, const float* __restrict__ wfc1,
    const float* __restrict__ wfc2)
{
    int b = blockIdx.x;
    const float* W; __half* Th; int K, N, nbx;
    if (b < 288)       { W = w2;   Th = g_w2h;  K = 384;  N = 768;  nbx = 24; }
    else if (b < 2016) { b -= 288;  W = wqkv; Th = g_qkvh; K = 768;  N = 2304; nbx = 72; }
    else if (b < 2592) { b -= 2016; W = wo;   Th = g_woh;  K = 768;  N = 768;  nbx = 24; }
    else if (b < 4896) { b -= 2592; W = wfc1; Th = g_fc1h; K = 768;  N = 3072; nbx = 96; }
    else               { b -= 4896; W = wfc2; Th = g_fc2h; K = 3072; N = 768;  nbx = 24; }
    int nb = (b % nbx) * 32, kb = (b / nbx) * 32;

    __shared__ float t[32][33];
    int x = threadIdx.x, y = threadIdx.y;   // (32, 8)
#pragma unroll
    for (int i = 0; i < 32; i += 8)
        t[y + i][x] = W[(size_t)(kb + y + i) * N + nb + x];
    __syncthreads();
#pragma unroll
    for (int i = 0; i < 32; i += 8)
        Th[(size_t)(nb + y + i) * K + kb + x] = __float2half_rn(t[x][y + i]);
}

// ---------------- embed stage 1: h = relu(box @ w1), K=4 --------------------
__global__ void embed_h_k(const float* __restrict__ box, const float* __restrict__ w1)
{
    int idx = blockIdx.x * blockDim.x + threadIdx.x;
    if (idx >= NTOK * 384) return;
    int m = idx / 384, j = idx - m * 384;
    const float* bx = box + m * 4;
    float acc = bx[0] * w1[j] + bx[1] * w1[384 + j] + bx[2] * w1[768 + j] + bx[3] * w1[1152 + j];
    acc = fmaxf(acc, 0.0f);
    split_f16(acc, g_h_hi[idx], g_h_lo[idx]);
}

// ================= HMMA fp16 2-term GEMM, cp.async double-buffered ==========
// C[M,N] = epi(A @ B^T). A hi/lo [M][K] fp16 (A = Ah+Al), B [N][K] fp16.
// CTA tile TM x 128 (TM = 128 or 64), 8 warps (2m x 4n), k-chunk 32.
// EPI: 0 plain fp32; 1 relu + res[(m%LL)*N+n]; 2 +bias+res[m*N+n]; 3 +bias, gelu -> split fp16
template<int EPI, int TM>
__global__ void __launch_bounds__(256)
hgemm_k(const __half* __restrict__ Ahi, const __half* __restrict__ Alo,
        const __half* __restrict__ Bh16,
        const float* __restrict__ bias, const float* __restrict__ res,
        float* __restrict__ Cf, __half* __restrict__ Chi, __half* __restrict__ Clo,
        int M, int N, int K)
{
    extern __shared__ __align__(16) __half smbuf[];
    constexpr int MT = TM / 32;                      // warp m-subtiles of 16
    constexpr uint32_t STG_B = (uint32_t)TM * 160 + 128 * 80;  // bytes per stage
    const uint32_t offAh = 0;
    const uint32_t offAl = (uint32_t)TM * 80;
    const uint32_t offB  = (uint32_t)TM * 160;

    const int tid = threadIdx.x;
    const int wid = tid >> 5, lane = tid & 31;
    const int wm = wid >> 2, wn = wid & 3;
    const int m0 = blockIdx.y * TM, n0 = blockIdx.x * 128;
    const uint32_t smb = smem_u32(smbuf);

    const int nch = K >> 5;

    auto load_stage = [&](int st, int kb) {
        uint32_t sb = smb + (uint32_t)st * STG_B;
#pragma unroll
        for (int s = tid; s < TM * 4; s += 256) {
            int row = s >> 2, seg = s & 3;
            uint32_t d = sb + (uint32_t)(row * 80 + seg * 16);
            size_t go = (size_t)(m0 + row) * K + kb + seg * 8;
            cpa16(d + offAh, Ahi + go);
            cpa16(d + offAl, Alo + go);
        }
#pragma unroll
        for (int s = tid; s < 512; s += 256) {
            int row = s >> 2, seg = s & 3;
            uint32_t d = sb + (uint32_t)(row * 80 + seg * 16);
            size_t go = (size_t)(n0 + row) * K + kb + seg * 8;
            cpa16(d + offB, Bh16 + go);
        }
    };

    const uint32_t a_lo = (uint32_t)(lane & 15) * 80 + (uint32_t)(lane >> 4) * 16;
    const uint32_t a_wb = (uint32_t)(wm * (TM / 2)) * 80;
    const uint32_t b_wb = (uint32_t)(wn * 32) * 80;

    float c[MT][4][4] = {};

    load_stage(0, 0);
    CP_COMMIT();

    for (int ch = 0; ch < nch; ch++) {
        CP_WAIT0();
        __syncthreads();
        if (ch + 1 < nch) {
            load_stage((ch + 1) & 1, (ch + 1) << 5);
            CP_COMMIT();
        }
        uint32_t sb = smb + (uint32_t)(ch & 1) * STG_B;
#pragma unroll
        for (int ks = 0; ks < 2; ks++) {
            uint32_t koff = ks * 32;
            uint32_t ah[MT][4], al[MT][4], bh[2][4];
#pragma unroll
            for (int mt = 0; mt < MT; mt++) {
                uint32_t off = a_wb + (uint32_t)(mt * 16) * 80 + a_lo + koff;
                ldsm4(ah[mt], sb + offAh + off);
                ldsm4(al[mt], sb + offAl + off);
            }
#pragma unroll
            for (int p = 0; p < 2; p++) {
                uint32_t off = b_wb + (uint32_t)(p * 16) * 80 + a_lo + koff;
                ldsm4(bh[p], sb + offB + off);
            }
#pragma unroll
            for (int mt = 0; mt < MT; mt++) {
#pragma unroll
                for (int p = 0; p < 2; p++) {
#pragma unroll
                    for (int s = 0; s < 2; s++) {
                        int nt = p * 2 + s;
                        uint32_t b0 = bh[p][s], b1 = bh[p][s + 2];
                        mma16816(c[mt][nt], ah[mt], b0, b1);
                        mma16816(c[mt][nt], al[mt], b0, b1);
                    }
                }
            }
        }
        __syncthreads();
    }

    // -------- epilogue: direct register -> gmem ------------------------------
    const int rbase = m0 + wm * (TM / 2) + (lane >> 2);
    const int cbase = n0 + wn * 32 + (lane & 3) * 2;
#pragma unroll
    for (int mt = 0; mt < MT; mt++) {
#pragma unroll
        for (int rr = 0; rr < 2; rr++) {
            int m = rbase + mt * 16 + rr * 8;
#pragma unroll
            for (int nt = 0; nt < 4; nt++) {
                int n = cbase + nt * 8;
                float v0 = c[mt][nt][rr * 2 + 0];
                float v1 = c[mt][nt][rr * 2 + 1];
                if (EPI == 1) {
                    const float* rp = res + (size_t)(m % LL) * N + n;
                    v0 = fmaxf(v0, 0.0f) + rp[0];
                    v1 = fmaxf(v1, 0.0f) + rp[1];
                    *(float2*)(Cf + (size_t)m * N + n) = make_float2(v0, v1);
                } else if (EPI == 2) {
                    const float* rp = res + (size_t)m * N + n;
                    v0 += bias[n] + rp[0];
                    v1 += bias[n + 1] + rp[1];
                    *(float2*)(Cf + (size_t)m * N + n) = make_float2(v0, v1);
                } else if (EPI == 3) {
                    v0 += bias[n];
                    v1 += bias[n + 1];
                    v0 = 0.5f * v0 * (1.0f + erff(v0 * 0.70710678118654752f));
                    v1 = 0.5f * v1 * (1.0f + erff(v1 * 0.70710678118654752f));
                    __half h0, l0, h1, l1;
                    split_f16(v0, h0, l0);
                    split_f16(v1, h1, l1);
                    __half2 hp; hp.x = h0; hp.y = h1;
                    __half2 lp; lp.x = l0; lp.y = l1;
                    *(__half2*)(Chi + (size_t)m * N + n) = hp;
                    *(__half2*)(Clo + (size_t)m * N + n) = lp;
                } else {
                    *(float2*)(Cf + (size_t)m * N + n) = make_float2(v0, v1);
                }
            }
        }
    }
}

// ---------------- layernorm: one block per row, split-fp16 output -----------
__global__ void ln_k(const float* __restrict__ X, const float* __restrict__ g,
                     const float* __restrict__ b,
                     __half* __restrict__ Yhi, __half* __restrict__ Ylo)
{
    int row = blockIdx.x;
    const float* x = X + (size_t)row * DD;
    int tid = threadIdx.x;
    float v[3];
    float s = 0.f, sq = 0.f;
#pragma unroll
    for (int r = 0; r < 3; r++) {
        v[r] = x[tid + r * 256];
        s += v[r];
        sq += v[r] * v[r];
    }
    __shared__ float red0[8], red1[8];
#pragma unroll
    for (int off = 16; off; off >>= 1) {
        s += __shfl_down_sync(0xffffffffu, s, off);
        sq += __shfl_down_sync(0xffffffffu, sq, off);
    }
    if ((tid & 31) == 0) { red0[tid >> 5] = s; red1[tid >> 5] = sq; }
    __syncthreads();
    s = 0.f; sq = 0.f;
#pragma unroll
    for (int i = 0; i < 8; i++) { s += red0[i]; sq += red1[i]; }
    float mean = s * (1.0f / DD);
    float var = sq * (1.0f / DD) - mean * mean;
    float rstd = rsqrtf(var + 1e-5f);
#pragma unroll
    for (int r = 0; r < 3; r++) {
        int c = tid + r * 256;
        float y = (v[r] - mean) * rstd * g[c] + b[c];
        split_f16(y, Yhi[(size_t)row * DD + c], Ylo[(size_t)row * DD + c]);
    }
}

// ---------------- attention: one block per (b,h), 256 threads ---------------
__global__ void attn_k(const float* __restrict__ qkv,
                       __half* __restrict__ Yhi, __half* __restrict__ Ylo)
{
    extern __shared__ float sm[];
    float* Ks = sm;
    float* Vs = Ks + LL * 65;
    float* Ps = Vs + LL * 65;
    float* Qs = Ps + 8 * LL;

    int bh = blockIdx.x;
    int b = bh / NHH, h = bh - b * NHH;
    int tid = threadIdx.x;

    for (int idx = tid; idx < LL * DHH; idx += 256) {
        int j = idx >> 6, d = idx & 63;
        size_t base = (size_t)(b * LL + j) * 2304 + h * 64 + d;
        Ks[j * 65 + d] = qkv[base + 768];
        Vs[j * 65 + d] = qkv[base + 1536];
    }
    __syncthreads();

    int w = tid >> 5, ln = tid & 31;
    float* ps = Ps + w * LL;
    float* qs = Qs + w * 64;

    for (int r = w; r < LL; r += 8) {
        size_t qb = (size_t)(b * LL + r) * 2304 + h * 64;
        qs[ln]      = qkv[qb + ln];
        qs[ln + 32] = qkv[qb + ln + 32];
        __syncwarp();
        float sc[5];
#pragma unroll
        for (int k5 = 0; k5 < 5; k5++) {
            int j = ln + k5 * 32;
            float a = 0.f;
#pragma unroll 8
            for (int d = 0; d < 64; d++) a = fmaf(qs[d], Ks[j * 65 + d], a);
            sc[k5] = a * 0.125f;
        }
        float mx = sc[0];
#pragma unroll
        for (int k5 = 1; k5 < 5; k5++) mx = fmaxf(mx, sc[k5]);
#pragma unroll
        for (int off = 16; off; off >>= 1) mx = fmaxf(mx, __shfl_xor_sync(0xffffffffu, mx, off));
        float sum = 0.f;
#pragma unroll
        for (int k5 = 0; k5 < 5; k5++) { sc[k5] = __expf(sc[k5] - mx); sum += sc[k5]; }
#pragma unroll
        for (int off = 16; off; off >>= 1) sum += __shfl_xor_sync(0xffffffffu, sum, off);
        float inv = 1.0f / sum;
#pragma unroll
        for (int k5 = 0; k5 < 5; k5++) ps[ln + k5 * 32] = sc[k5] * inv;
        __syncwarp();
        float o0 = 0.f, o1 = 0.f;
#pragma unroll 8
        for (int j = 0; j < LL; j++) {
            float p = ps[j];
            o0 = fmaf(p, Vs[j * 65 + ln], o0);
            o1 = fmaf(p, Vs[j * 65 + ln + 32], o1);
        }
        size_t ob = (size_t)(b * LL + r) * DD + h * 64;
        split_f16(o0, Yhi[ob + ln], Ylo[ob + ln]);
        split_f16(o1, Yhi[ob + ln + 32], Ylo[ob + ln + 32]);
        __syncwarp();
    }
}

// ---------------- box-mask scatter + temporal mean ---------------------------
__global__ void grid_k(const float* __restrict__ box, float* __restrict__ out)
{
    int blk = blockIdx.x;
    int w = blk % GW;
    int hh = (blk / GW) % GH;
    int tg = (blk / (GW * GH)) & 7;
    int b = blk / (GW * GH * 8);
    int tid = threadIdx.x;

    __shared__ float flg[20];
    if (tid < 20) {
        int t = tg * 2 + tid / 10;
        int o = tid % 10;
        const float* bx = box + (size_t)((b * TT + t) * OO + o) * 4;
        float x1 = fminf(bx[0], bx[2]), x2 = fmaxf(bx[0], bx[2]);
        float y1 = fminf(bx[1], bx[3]), y2 = fmaxf(bx[1], bx[3]);
        float cy = (hh + 0.5f) / 14.0f;
        float cx = (w + 0.5f) / 14.0f;
        flg[tid] = (cy >= y1 && cy <= y2 && cx >= x1 && cx <= x2) ? 1.0f : 0.0f;
    }
    __syncthreads();

    float a0 = 0.f, a1 = 0.f, a2 = 0.f;
#pragma unroll
    for (int e = 0; e < 20; e++) {
        if (flg[e] > 0.f) {
            const float* f = g_x + (size_t)(b * LL + (tg * 2 + e / 10) * OO + (e % 10)) * DD + tid;
            a0 += f[0];
            a1 += f[256];
            a2 += f[512];
        }
    }
    size_t ob = (size_t)blk * DD + tid;
    out[ob]       = 0.5f * a0;
    out[ob + 256] = 0.5f * a1;
    out[ob + 512] = 0.5f * a2;
}

// ---------------- launch ------------------------------------------------------
extern "C" void kernel_launch(void* const* d_in, const int* in_sizes, int n_in,
                              void* d_out, int out_size)
{
    const float* box  = (const float*)d_in[0];
    const float* cat  = (const float*)d_in[1];
    const float* w1   = (const float*)d_in[2];
    const float* w2   = (const float*)d_in[3];
    const float* ln1g = (const float*)d_in[4];
    const float* ln1b = (const float*)d_in[5];
    const float* wqkv = (const float*)d_in[6];
    const float* wo   = (const float*)d_in[7];
    const float* bo   = (const float*)d_in[8];
    const float* ln2g = (const float*)d_in[9];
    const float* ln2b = (const float*)d_in[10];
    const float* wfc1 = (const float*)d_in[11];
    const float* bfc1 = (const float*)d_in[12];
    const float* wfc2 = (const float*)d_in[13];
    const float* bfc2 = (const float*)d_in[14];
    float* out = (float*)d_out;

    float *gx, *gqkv;
    __half *ghh, *ghl, *ghnh, *ghnl, *gatth, *gattl, *gffnh, *gffnl;
    __half *w2h, *qkh, *woh, *f1h, *f2h;
    cudaGetSymbolAddress((void**)&gx,    g_x);
    cudaGetSymbolAddress((void**)&gqkv,  g_qkv);
    cudaGetSymbolAddress((void**)&ghh,   g_h_hi);
    cudaGetSymbolAddress((void**)&ghl,   g_h_lo);
    cudaGetSymbolAddress((void**)&ghnh,  g_hn_hi);
    cudaGetSymbolAddress((void**)&ghnl,  g_hn_lo);
    cudaGetSymbolAddress((void**)&gatth, g_att_hi);
    cudaGetSymbolAddress((void**)&gattl, g_att_lo);
    cudaGetSymbolAddress((void**)&gffnh, g_ffn_hi);
    cudaGetSymbolAddress((void**)&gffnl, g_ffn_lo);
    cudaGetSymbolAddress((void**)&w2h,   g_w2h);
    cudaGetSymbolAddress((void**)&qkh,   g_qkvh);
    cudaGetSymbolAddress((void**)&woh,   g_woh);
    cudaGetSymbolAddress((void**)&f1h,   g_fc1h);
    cudaGetSymbolAddress((void**)&f2h,   g_fc2h);

    const int attn_smem = (LL * 65 * 2 + 8 * LL + 8 * 64) * (int)sizeof(float);
    cudaFuncSetAttribute(attn_k, cudaFuncAttributeMaxDynamicSharedMemorySize, attn_smem);

    const int smem128 = (128 * 160 + 128 * 80) * 2;  // 61440
    const int smem64  = (64 * 160 + 128 * 80) * 2;   // 40960
    cudaFuncSetAttribute(hgemm_k<0, 128>, cudaFuncAttributeMaxDynamicSharedMemorySize, smem128);
    cudaFuncSetAttribute(hgemm_k<3, 128>, cudaFuncAttributeMaxDynamicSharedMemorySize, smem128);
    cudaFuncSetAttribute(hgemm_k<1, 64>,  cudaFuncAttributeMaxDynamicSharedMemorySize, smem64);
    cudaFuncSetAttribute(hgemm_k<2, 64>,  cudaFuncAttributeMaxDynamicSharedMemorySize, smem64);

    // weight transpose: single fused launch
    tsplit_all_k<<<7200, dim3(32, 8)>>>(w2, wqkv, wo, wfc1, wfc2);

    // 1) h = relu(box @ w1)
    embed_h_k<<<(NTOK * 384 + 255) / 256, 256>>>(box, w1);

    // 2) x = relu(h @ w2) + cat
    hgemm_k<1, 64><<<dim3(DD / 128, NTOK / 64), 256, smem64>>>(
        ghh, ghl, w2h, nullptr, cat, gx, nullptr, nullptr, NTOK, DD, 384);

    // 3) hn = LN1(x)
    ln_k<<<NTOK, 256>>>(gx, ln1g, ln1b, ghnh, ghnl);

    // 4) qkv = hn @ wqkv
    hgemm_k<0, 128><<<dim3(3 * DD / 128, NTOK / 128), 256, smem128>>>(
        ghnh, ghnl, qkh, nullptr, nullptr, gqkv, nullptr, nullptr, NTOK, 3 * DD, DD);

    // 5) attention
    attn_k<<<BB * NHH, 256, attn_smem>>>(gqkv, gatth, gattl);

    // 6) x = x + att @ wo + bo
    hgemm_k<2, 64><<<dim3(DD / 128, NTOK / 64), 256, smem64>>>(
        gatth, gattl, woh, bo, gx, gx, nullptr, nullptr, NTOK, DD, DD);

    // 7) hn = LN2(x)
    ln_k<<<NTOK, 256>>>(gx, ln2g, ln2b, ghnh, ghnl);

    // 8) ffn = gelu(hn @ wfc1 + bfc1) -> split fp16
    hgemm_k<3, 128><<<dim3(4 * DD / 128, NTOK / 128), 256, smem128>>>(
        ghnh, ghnl, f1h, bfc1, nullptr, nullptr, gffnh, gffnl, NTOK, 4 * DD, DD);

    // 9) x = x + ffn @ wfc2 + bfc2
    hgemm_k<2, 64><<<dim3(DD / 128, NTOK / 64), 256, smem64>>>(
        gffnh, gffnl, f2h, bfc2, gx, gx, nullptr, nullptr, NTOK, DD, 4 * DD);

    // 10) mask scatter + temporal mean -> out
    grid_k<<<BB * 8 * GH * GW, 256>>>(box, out);
}

// round 6
// speedup vs baseline: 2.7313x; 1.1885x over previous
#include <cuda_runtime.h>
#include <cuda_fp16.h>
#include <math.h>
#include <stdint.h>

#define BB   16
#define TT   16
#define OO   10
#define LL   160      // T*O
#define DD   768
#define NHH  12
#define DHH  64
#define GH   14
#define GW   14
#define NTOK (BB*LL)  // 2560

// ---------------- scratch (device globals; no runtime alloc allowed) --------
__device__ float g_x  [NTOK*DD];       // residual stream, fp32
__device__ float g_qkv[NTOK*3*DD];     // fp32, read by attention

// split-fp16 activation buffers (hi + lo)
__device__ __half g_h_hi  [NTOK*384];
__device__ __half g_h_lo  [NTOK*384];
__device__ __half g_hn_hi [NTOK*DD];
__device__ __half g_hn_lo [NTOK*DD];
__device__ __half g_att_hi[NTOK*DD];
__device__ __half g_att_lo[NTOK*DD];
__device__ __half g_ffn_hi[NTOK*4*DD];
__device__ __half g_ffn_lo[NTOK*4*DD];

// transposed weights [N][K], single fp16 (round-to-nearest)
__device__ __half g_w2h  [DD*384];
__device__ __half g_qkvh [3*DD*DD];
__device__ __half g_woh  [DD*DD];
__device__ __half g_fc1h [4*DD*DD];
__device__ __half g_fc2h [DD*4*DD];

// ============================ helpers ========================================
__device__ __forceinline__ uint32_t smem_u32(const void* p) {
    uint32_t a;
    asm("{ .reg .u64 t; cvta.to.shared.u64 t, %1; cvt.u32.u64 %0, t; }" : "=r"(a) : "l"(p));
    return a;
}
__device__ __forceinline__ void split_f16(float v, __half& h, __half& l) {
    h = __float2half_rn(v);
    l = __float2half_rn(v - __half2float(h));
}
__device__ __forceinline__ uint32_t h2pack(__half a, __half b) {
    __half2 h; h.x = a; h.y = b;
    return *(uint32_t*)&h;
}
__device__ __forceinline__ void ldsm4(uint32_t* r, uint32_t addr) {
    asm volatile("ldmatrix.sync.aligned.m8n8.x4.shared.b16 {%0,%1,%2,%3}, [%4];"
        : "=r"(r[0]), "=r"(r[1]), "=r"(r[2]), "=r"(r[3]) : "r"(addr));
}
__device__ __forceinline__ void mma16816(float* c, const uint32_t* a, uint32_t b0, uint32_t b1) {
    asm volatile(
        "mma.sync.aligned.m16n8k16.row.col.f32.f16.f16.f32 "
        "{%0,%1,%2,%3}, {%4,%5,%6,%7}, {%8,%9}, {%0,%1,%2,%3};"
        : "+f"(c[0]), "+f"(c[1]), "+f"(c[2]), "+f"(c[3])
        : "r"(a[0]), "r"(a[1]), "r"(a[2]), "r"(a[3]), "r"(b0), "r"(b1));
}
__device__ __forceinline__ void cpa16(uint32_t dst, const void* src) {
    asm volatile("cp.async.cg.shared.global [%0], [%1], 16;" :: "r"(dst), "l"(src) : "memory");
}
#define CP_COMMIT() asm volatile("cp.async.commit_group;" ::: "memory")
#define CP_WAIT0()  asm volatile("cp.async.wait_group 0;" ::: "memory")

// ---------------- fused weight transpose (one launch, fp16 RN) --------------
__global__ void tsplit_all_k(
    const float* __restrict__ w2, const float* __restrict__ wqkv,
    const float* __restrict__ wo, const float* __restrict__ wfc1,
    const float* __restrict__ wfc2)
{
    int b = blockIdx.x;
    const float* W; __half* Th; int K, N, nbx;
    if (b < 288)       { W = w2;   Th = g_w2h;  K = 384;  N = 768;  nbx = 24; }
    else if (b < 2016) { b -= 288;  W = wqkv; Th = g_qkvh; K = 768;  N = 2304; nbx = 72; }
    else if (b < 2592) { b -= 2016; W = wo;   Th = g_woh;  K = 768;  N = 768;  nbx = 24; }
    else if (b < 4896) { b -= 2592; W = wfc1; Th = g_fc1h; K = 768;  N = 3072; nbx = 96; }
    else               { b -= 4896; W = wfc2; Th = g_fc2h; K = 3072; N = 768;  nbx = 24; }
    int nb = (b % nbx) * 32, kb = (b / nbx) * 32;

    __shared__ float t[32][33];
    int x = threadIdx.x, y = threadIdx.y;   // (32, 8)
#pragma unroll
    for (int i = 0; i < 32; i += 8)
        t[y + i][x] = W[(size_t)(kb + y + i) * N + nb + x];
    __syncthreads();
#pragma unroll
    for (int i = 0; i < 32; i += 8)
        Th[(size_t)(nb + y + i) * K + kb + x] = __float2half_rn(t[x][y + i]);
}

// ---------------- embed stage 1: h = relu(box @ w1), K=4 --------------------
__global__ void embed_h_k(const float* __restrict__ box, const float* __restrict__ w1)
{
    int idx = blockIdx.x * blockDim.x + threadIdx.x;
    if (idx >= NTOK * 384) return;
    int m = idx / 384, j = idx - m * 384;
    const float* bx = box + m * 4;
    float acc = bx[0] * w1[j] + bx[1] * w1[384 + j] + bx[2] * w1[768 + j] + bx[3] * w1[1152 + j];
    acc = fmaxf(acc, 0.0f);
    split_f16(acc, g_h_hi[idx], g_h_lo[idx]);
}

// ================= HMMA fp16 2-term GEMM, cp.async double-buffered ==========
template<int EPI, int TM>
__global__ void __launch_bounds__(256)
hgemm_k(const __half* __restrict__ Ahi, const __half* __restrict__ Alo,
        const __half* __restrict__ Bh16,
        const float* __restrict__ bias, const float* __restrict__ res,
        float* __restrict__ Cf, __half* __restrict__ Chi, __half* __restrict__ Clo,
        int M, int N, int K)
{
    extern __shared__ __align__(16) __half smbuf[];
    constexpr int MT = TM / 32;
    constexpr uint32_t STG_B = (uint32_t)TM * 160 + 128 * 80;
    const uint32_t offAh = 0;
    const uint32_t offAl = (uint32_t)TM * 80;
    const uint32_t offB  = (uint32_t)TM * 160;

    const int tid = threadIdx.x;
    const int wid = tid >> 5, lane = tid & 31;
    const int wm = wid >> 2, wn = wid & 3;
    const int m0 = blockIdx.y * TM, n0 = blockIdx.x * 128;
    const uint32_t smb = smem_u32(smbuf);

    const int nch = K >> 5;

    auto load_stage = [&](int st, int kb) {
        uint32_t sb = smb + (uint32_t)st * STG_B;
#pragma unroll
        for (int s = tid; s < TM * 4; s += 256) {
            int row = s >> 2, seg = s & 3;
            uint32_t d = sb + (uint32_t)(row * 80 + seg * 16);
            size_t go = (size_t)(m0 + row) * K + kb + seg * 8;
            cpa16(d + offAh, Ahi + go);
            cpa16(d + offAl, Alo + go);
        }
#pragma unroll
        for (int s = tid; s < 512; s += 256) {
            int row = s >> 2, seg = s & 3;
            uint32_t d = sb + (uint32_t)(row * 80 + seg * 16);
            size_t go = (size_t)(n0 + row) * K + kb + seg * 8;
            cpa16(d + offB, Bh16 + go);
        }
    };

    const uint32_t a_lo = (uint32_t)(lane & 15) * 80 + (uint32_t)(lane >> 4) * 16;
    const uint32_t a_wb = (uint32_t)(wm * (TM / 2)) * 80;
    const uint32_t b_wb = (uint32_t)(wn * 32) * 80;

    float c[MT][4][4] = {};

    load_stage(0, 0);
    CP_COMMIT();

    for (int ch = 0; ch < nch; ch++) {
        CP_WAIT0();
        __syncthreads();
        if (ch + 1 < nch) {
            load_stage((ch + 1) & 1, (ch + 1) << 5);
            CP_COMMIT();
        }
        uint32_t sb = smb + (uint32_t)(ch & 1) * STG_B;
#pragma unroll
        for (int ks = 0; ks < 2; ks++) {
            uint32_t koff = ks * 32;
            uint32_t ah[MT][4], al[MT][4], bh[2][4];
#pragma unroll
            for (int mt = 0; mt < MT; mt++) {
                uint32_t off = a_wb + (uint32_t)(mt * 16) * 80 + a_lo + koff;
                ldsm4(ah[mt], sb + offAh + off);
                ldsm4(al[mt], sb + offAl + off);
            }
#pragma unroll
            for (int p = 0; p < 2; p++) {
                uint32_t off = b_wb + (uint32_t)(p * 16) * 80 + a_lo + koff;
                ldsm4(bh[p], sb + offB + off);
            }
#pragma unroll
            for (int mt = 0; mt < MT; mt++) {
#pragma unroll
                for (int p = 0; p < 2; p++) {
#pragma unroll
                    for (int s = 0; s < 2; s++) {
                        int nt = p * 2 + s;
                        uint32_t b0 = bh[p][s], b1 = bh[p][s + 2];
                        mma16816(c[mt][nt], ah[mt], b0, b1);
                        mma16816(c[mt][nt], al[mt], b0, b1);
                    }
                }
            }
        }
        __syncthreads();
    }

    const int rbase = m0 + wm * (TM / 2) + (lane >> 2);
    const int cbase = n0 + wn * 32 + (lane & 3) * 2;
#pragma unroll
    for (int mt = 0; mt < MT; mt++) {
#pragma unroll
        for (int rr = 0; rr < 2; rr++) {
            int m = rbase + mt * 16 + rr * 8;
#pragma unroll
            for (int nt = 0; nt < 4; nt++) {
                int n = cbase + nt * 8;
                float v0 = c[mt][nt][rr * 2 + 0];
                float v1 = c[mt][nt][rr * 2 + 1];
                if (EPI == 1) {
                    const float* rp = res + (size_t)(m % LL) * N + n;
                    v0 = fmaxf(v0, 0.0f) + rp[0];
                    v1 = fmaxf(v1, 0.0f) + rp[1];
                    *(float2*)(Cf + (size_t)m * N + n) = make_float2(v0, v1);
                } else if (EPI == 2) {
                    const float* rp = res + (size_t)m * N + n;
                    v0 += bias[n] + rp[0];
                    v1 += bias[n + 1] + rp[1];
                    *(float2*)(Cf + (size_t)m * N + n) = make_float2(v0, v1);
                } else if (EPI == 3) {
                    v0 += bias[n];
                    v1 += bias[n + 1];
                    v0 = 0.5f * v0 * (1.0f + erff(v0 * 0.70710678118654752f));
                    v1 = 0.5f * v1 * (1.0f + erff(v1 * 0.70710678118654752f));
                    __half h0, l0, h1, l1;
                    split_f16(v0, h0, l0);
                    split_f16(v1, h1, l1);
                    *(__half2*)(Chi + (size_t)m * N + n) = __halves2half2(h0, h1);
                    *(__half2*)(Clo + (size_t)m * N + n) = __halves2half2(l0, l1);
                } else {
                    *(float2*)(Cf + (size_t)m * N + n) = make_float2(v0, v1);
                }
            }
        }
    }
}

// ================= HMMA attention: one block per (b,h), 160 threads =========
// Q·K^T and P·V via m16n8k16 with 3-term split (error-neutral vs fp32).
// smem: Kh/Kl [160][72] halves (144B stride), Vth/Vtl [64][168] halves (336B stride)
#define KSTR 72
#define VSTR 168
#define ATT_SMEM ((2*160*KSTR + 2*64*VSTR) * 2)   // 89088 bytes

__global__ void __launch_bounds__(160)
attn_k(const float* __restrict__ qkv, __half* __restrict__ Yhi, __half* __restrict__ Ylo)
{
    extern __shared__ __half smh[];
    __half* sKh = smh;
    __half* sKl = smh + 160 * KSTR;
    __half* sVh = smh + 2 * 160 * KSTR;
    __half* sVl = smh + 2 * 160 * KSTR + 64 * VSTR;

    const int bh = blockIdx.x;
    const int b = bh / NHH, h = bh - b * NHH;
    const int tid = threadIdx.x;
    const int wid = tid >> 5, lane = tid & 31;
    const int g = lane >> 2, t = lane & 3;

    // ---- stage K, V^T (split fp16) ----
    for (int idx = tid; idx < 160 * 64; idx += 160) {
        int row = idx >> 6, col = idx & 63;
        size_t base = (size_t)(b * LL + row) * 2304 + h * 64 + col;
        float kv = qkv[base + 768];
        float vv = qkv[base + 1536];
        __half khh, kll; split_f16(kv, khh, kll);
        sKh[row * KSTR + col] = khh;
        sKl[row * KSTR + col] = kll;
        __half vhh, vll; split_f16(vv, vhh, vll);
        sVh[col * VSTR + row] = vhh;
        sVl[col * VSTR + row] = vll;
    }
    __syncthreads();

    const uint32_t kh_b = smem_u32(sKh), kl_b = smem_u32(sKl);
    const uint32_t vh_b = smem_u32(sVh), vl_b = smem_u32(sVl);
    const uint32_t lrow = (uint32_t)(lane & 15);
    const uint32_t lseg = (uint32_t)(lane >> 4) * 16;

#pragma unroll
    for (int mi = 0; mi < 2; mi++) {
        const int mt = wid * 2 + mi;
        const size_t qrow0 = (size_t)(b * LL + mt * 16 + g) * 2304 + h * 64;
        const size_t qrow1 = qrow0 + 8 * 2304;

        // ---- Q a-frags (scaled by exact 0.125 before split) ----
        uint32_t qh[4][4], ql[4][4];
#pragma unroll
        for (int kt = 0; kt < 4; kt++) {
            int c0 = kt * 16 + 2 * t;
            float2 x0 = *(const float2*)(qkv + qrow0 + c0);
            float2 x1 = *(const float2*)(qkv + qrow1 + c0);
            float2 x2 = *(const float2*)(qkv + qrow0 + c0 + 8);
            float2 x3 = *(const float2*)(qkv + qrow1 + c0 + 8);
            float f[4][2] = {{x0.x * 0.125f, x0.y * 0.125f}, {x1.x * 0.125f, x1.y * 0.125f},
                             {x2.x * 0.125f, x2.y * 0.125f}, {x3.x * 0.125f, x3.y * 0.125f}};
#pragma unroll
            for (int a = 0; a < 4; a++) {
                __half h0, l0, h1, l1;
                split_f16(f[a][0], h0, l0);
                split_f16(f[a][1], h1, l1);
                qh[kt][a] = h2pack(h0, h1);
                ql[kt][a] = h2pack(l0, l1);
            }
        }

        // ---- scores S = (Q*0.125) @ K^T, fp32 accum ----
        float c[20][4];
#pragma unroll
        for (int nt = 0; nt < 20; nt++)
#pragma unroll
            for (int e = 0; e < 4; e++) c[nt][e] = 0.f;

        for (int n2 = 0; n2 < 10; n2++) {
            uint32_t roff = (uint32_t)(n2 * 16) * 144 + lrow * 144 + lseg;
#pragma unroll
            for (int kt = 0; kt < 4; kt++) {
                uint32_t kfh[4], kfl[4];
                ldsm4(kfh, kh_b + roff + kt * 32);
                ldsm4(kfl, kl_b + roff + kt * 32);
#pragma unroll
                for (int s = 0; s < 2; s++) {
                    float* cc = c[n2 * 2 + s];
                    mma16816(cc, qh[kt], kfh[s], kfh[s + 2]);
                    mma16816(cc, ql[kt], kfh[s], kfh[s + 2]);
                    mma16816(cc, qh[kt], kfl[s], kfl[s + 2]);
                }
            }
        }

        // ---- softmax (rows r0 = regs 0,1; r1 = regs 2,3) ----
        float m0 = -1e30f, m1 = -1e30f;
#pragma unroll
        for (int nt = 0; nt < 20; nt++) {
            m0 = fmaxf(m0, fmaxf(c[nt][0], c[nt][1]));
            m1 = fmaxf(m1, fmaxf(c[nt][2], c[nt][3]));
        }
#pragma unroll
        for (int off = 1; off <= 2; off <<= 1) {
            m0 = fmaxf(m0, __shfl_xor_sync(0xffffffffu, m0, off));
            m1 = fmaxf(m1, __shfl_xor_sync(0xffffffffu, m1, off));
        }
        float s0 = 0.f, s1 = 0.f;
#pragma unroll
        for (int nt = 0; nt < 20; nt++) {
            c[nt][0] = __expf(c[nt][0] - m0);
            c[nt][1] = __expf(c[nt][1] - m0);
            c[nt][2] = __expf(c[nt][2] - m1);
            c[nt][3] = __expf(c[nt][3] - m1);
            s0 += c[nt][0] + c[nt][1];
            s1 += c[nt][2] + c[nt][3];
        }
#pragma unroll
        for (int off = 1; off <= 2; off <<= 1) {
            s0 += __shfl_xor_sync(0xffffffffu, s0, off);
            s1 += __shfl_xor_sync(0xffffffffu, s1, off);
        }
        const float inv0 = 1.0f / s0, inv1 = 1.0f / s1;

        // ---- O = P @ V ----
        float o[8][4];
#pragma unroll
        for (int nt = 0; nt < 8; nt++)
#pragma unroll
            for (int e = 0; e < 4; e++) o[nt][e] = 0.f;

        for (int k2 = 0; k2 < 10; k2++) {
            uint32_t ph[4], pl[4];
            {
                const float* ca = c[2 * k2];
                const float* cb = c[2 * k2 + 1];
                __half ha, la, hb, lb;
                split_f16(ca[0], ha, la); split_f16(ca[1], hb, lb);
                ph[0] = h2pack(ha, hb); pl[0] = h2pack(la, lb);
                split_f16(ca[2], ha, la); split_f16(ca[3], hb, lb);
                ph[1] = h2pack(ha, hb); pl[1] = h2pack(la, lb);
                split_f16(cb[0], ha, la); split_f16(cb[1], hb, lb);
                ph[2] = h2pack(ha, hb); pl[2] = h2pack(la, lb);
                split_f16(cb[2], ha, la); split_f16(cb[3], hb, lb);
                ph[3] = h2pack(ha, hb); pl[3] = h2pack(la, lb);
            }
#pragma unroll
            for (int n2v = 0; n2v < 4; n2v++) {
                uint32_t roff = (uint32_t)(n2v * 16) * 336 + lrow * 336 + lseg + k2 * 32;
                uint32_t vfh[4], vfl[4];
                ldsm4(vfh, vh_b + roff);
                ldsm4(vfl, vl_b + roff);
#pragma unroll
                for (int s = 0; s < 2; s++) {
                    float* oo = o[n2v * 2 + s];
                    mma16816(oo, ph, vfh[s], vfh[s + 2]);
                    mma16816(oo, pl, vfh[s], vfh[s + 2]);
                    mma16816(oo, ph, vfl[s], vfl[s + 2]);
                }
            }
        }

        // ---- epilogue: normalize + split store ----
        const size_t row0 = (size_t)(b * LL + mt * 16 + g) * DD + h * 64;
        const size_t row1 = row0 + (size_t)8 * DD;
#pragma unroll
        for (int nt = 0; nt < 8; nt++) {
            int col = nt * 8 + 2 * t;
            float v0 = o[nt][0] * inv0, v1 = o[nt][1] * inv0;
            float v2 = o[nt][2] * inv1, v3 = o[nt][3] * inv1;
            __half h0, l0, h1, l1;
            split_f16(v0, h0, l0); split_f16(v1, h1, l1);
            *(__half2*)(Yhi + row0 + col) = __halves2half2(h0, h1);
            *(__half2*)(Ylo + row0 + col) = __halves2half2(l0, l1);
            split_f16(v2, h0, l0); split_f16(v3, h1, l1);
            *(__half2*)(Yhi + row1 + col) = __halves2half2(h0, h1);
            *(__half2*)(Ylo + row1 + col) = __halves2half2(l0, l1);
        }
    }
}

// ---------------- layernorm: one block per row, split-fp16 output -----------
__global__ void ln_k(const float* __restrict__ X, const float* __restrict__ g,
                     const float* __restrict__ b,
                     __half* __restrict__ Yhi, __half* __restrict__ Ylo)
{
    int row = blockIdx.x;
    const float* x = X + (size_t)row * DD;
    int tid = threadIdx.x;
    float v[3];
    float s = 0.f, sq = 0.f;
#pragma unroll
    for (int r = 0; r < 3; r++) {
        v[r] = x[tid + r * 256];
        s += v[r];
        sq += v[r] * v[r];
    }
    __shared__ float red0[8], red1[8];
#pragma unroll
    for (int off = 16; off; off >>= 1) {
        s += __shfl_down_sync(0xffffffffu, s, off);
        sq += __shfl_down_sync(0xffffffffu, sq, off);
    }
    if ((tid & 31) == 0) { red0[tid >> 5] = s; red1[tid >> 5] = sq; }
    __syncthreads();
    s = 0.f; sq = 0.f;
#pragma unroll
    for (int i = 0; i < 8; i++) { s += red0[i]; sq += red1[i]; }
    float mean = s * (1.0f / DD);
    float var = sq * (1.0f / DD) - mean * mean;
    float rstd = rsqrtf(var + 1e-5f);
#pragma unroll
    for (int r = 0; r < 3; r++) {
        int c = tid + r * 256;
        float y = (v[r] - mean) * rstd * g[c] + b[c];
        split_f16(y, Yhi[(size_t)row * DD + c], Ylo[(size_t)row * DD + c]);
    }
}

// ---------------- box-mask scatter + temporal mean ---------------------------
__global__ void grid_k(const float* __restrict__ box, float* __restrict__ out)
{
    int blk = blockIdx.x;
    int w = blk % GW;
    int hh = (blk / GW) % GH;
    int tg = (blk / (GW * GH)) & 7;
    int b = blk / (GW * GH * 8);
    int tid = threadIdx.x;

    __shared__ float flg[20];
    if (tid < 20) {
        int t = tg * 2 + tid / 10;
        int o = tid % 10;
        const float* bx = box + (size_t)((b * TT + t) * OO + o) * 4;
        float x1 = fminf(bx[0], bx[2]), x2 = fmaxf(bx[0], bx[2]);
        float y1 = fminf(bx[1], bx[3]), y2 = fmaxf(bx[1], bx[3]);
        float cy = (hh + 0.5f) / 14.0f;
        float cx = (w + 0.5f) / 14.0f;
        flg[tid] = (cy >= y1 && cy <= y2 && cx >= x1 && cx <= x2) ? 1.0f : 0.0f;
    }
    __syncthreads();

    float a0 = 0.f, a1 = 0.f, a2 = 0.f;
#pragma unroll
    for (int e = 0; e < 20; e++) {
        if (flg[e] > 0.f) {
            const float* f = g_x + (size_t)(b * LL + (tg * 2 + e / 10) * OO + (e % 10)) * DD + tid;
            a0 += f[0];
            a1 += f[256];
            a2 += f[512];
        }
    }
    size_t ob = (size_t)blk * DD + tid;
    out[ob]       = 0.5f * a0;
    out[ob + 256] = 0.5f * a1;
    out[ob + 512] = 0.5f * a2;
}

// ---------------- launch ------------------------------------------------------
extern "C" void kernel_launch(void* const* d_in, const int* in_sizes, int n_in,
                              void* d_out, int out_size)
{
    const float* box  = (const float*)d_in[0];
    const float* cat  = (const float*)d_in[1];
    const float* w1   = (const float*)d_in[2];
    const float* w2   = (const float*)d_in[3];
    const float* ln1g = (const float*)d_in[4];
    const float* ln1b = (const float*)d_in[5];
    const float* wqkv = (const float*)d_in[6];
    const float* wo   = (const float*)d_in[7];
    const float* bo   = (const float*)d_in[8];
    const float* ln2g = (const float*)d_in[9];
    const float* ln2b = (const float*)d_in[10];
    const float* wfc1 = (const float*)d_in[11];
    const float* bfc1 = (const float*)d_in[12];
    const float* wfc2 = (const float*)d_in[13];
    const float* bfc2 = (const float*)d_in[14];
    float* out = (float*)d_out;

    float *gx, *gqkv;
    __half *ghh, *ghl, *ghnh, *ghnl, *gatth, *gattl, *gffnh, *gffnl;
    __half *w2h, *qkh, *woh, *f1h, *f2h;
    cudaGetSymbolAddress((void**)&gx,    g_x);
    cudaGetSymbolAddress((void**)&gqkv,  g_qkv);
    cudaGetSymbolAddress((void**)&ghh,   g_h_hi);
    cudaGetSymbolAddress((void**)&ghl,   g_h_lo);
    cudaGetSymbolAddress((void**)&ghnh,  g_hn_hi);
    cudaGetSymbolAddress((void**)&ghnl,  g_hn_lo);
    cudaGetSymbolAddress((void**)&gatth, g_att_hi);
    cudaGetSymbolAddress((void**)&gattl, g_att_lo);
    cudaGetSymbolAddress((void**)&gffnh, g_ffn_hi);
    cudaGetSymbolAddress((void**)&gffnl, g_ffn_lo);
    cudaGetSymbolAddress((void**)&w2h,   g_w2h);
    cudaGetSymbolAddress((void**)&qkh,   g_qkvh);
    cudaGetSymbolAddress((void**)&woh,   g_woh);
    cudaGetSymbolAddress((void**)&f1h,   g_fc1h);
    cudaGetSymbolAddress((void**)&f2h,   g_fc2h);

    cudaFuncSetAttribute(attn_k, cudaFuncAttributeMaxDynamicSharedMemorySize, ATT_SMEM);

    const int smem128 = (128 * 160 + 128 * 80) * 2;  // 61440
    const int smem64  = (64 * 160 + 128 * 80) * 2;   // 40960
    cudaFuncSetAttribute(hgemm_k<0, 128>, cudaFuncAttributeMaxDynamicSharedMemorySize, smem128);
    cudaFuncSetAttribute(hgemm_k<3, 128>, cudaFuncAttributeMaxDynamicSharedMemorySize, smem128);
    cudaFuncSetAttribute(hgemm_k<1, 64>,  cudaFuncAttributeMaxDynamicSharedMemorySize, smem64);
    cudaFuncSetAttribute(hgemm_k<2, 64>,  cudaFuncAttributeMaxDynamicSharedMemorySize, smem64);

    tsplit_all_k<<<7200, dim3(32, 8)>>>(w2, wqkv, wo, wfc1, wfc2);

    embed_h_k<<<(NTOK * 384 + 255) / 256, 256>>>(box, w1);

    hgemm_k<1, 64><<<dim3(DD / 128, NTOK / 64), 256, smem64>>>(
        ghh, ghl, w2h, nullptr, cat, gx, nullptr, nullptr, NTOK, DD, 384);

    ln_k<<<NTOK, 256>>>(gx, ln1g, ln1b, ghnh, ghnl);

    hgemm_k<0, 128><<<dim3(3 * DD / 128, NTOK / 128), 256, smem128>>>(
        ghnh, ghnl, qkh, nullptr, nullptr, gqkv, nullptr, nullptr, NTOK, 3 * DD, DD);

    attn_k<<<BB * NHH, 160, ATT_SMEM>>>(gqkv, gatth, gattl);

    hgemm_k<2, 64><<<dim3(DD / 128, NTOK / 64), 256, smem64>>>(
        gatth, gattl, woh, bo, gx, gx, nullptr, nullptr, NTOK, DD, DD);

    ln_k<<<NTOK, 256>>>(gx, ln2g, ln2b, ghnh, ghnl);

    hgemm_k<3, 128><<<dim3(4 * DD / 128, NTOK / 128), 256, smem128>>>(
        ghnh, ghnl, f1h, bfc1, nullptr, nullptr, gffnh, gffnl, NTOK, 4 * DD, DD);

    hgemm_k<2, 64><<<dim3(DD / 128, NTOK / 64), 256, smem64>>>(
        gffnh, gffnl, f2h, bfc2, gx, gx, nullptr, nullptr, NTOK, DD, 4 * DD);

    grid_k<<<BB * 8 * GH * GW, 256>>>(box, out);
}

// round 7
// speedup vs baseline: 3.4156x; 1.2506x over previous
#include <cuda_runtime.h>
#include <cuda_fp16.h>
#include <math.h>
#include <stdint.h>

#define BB   16
#define TT   16
#define OO   10
#define LL   160      // T*O
#define DD   768
#define NHH  12
#define DHH  64
#define GH   14
#define GW   14
#define NTOK (BB*LL)  // 2560

// ---------------- scratch (device globals; no runtime alloc allowed) --------
__device__ float g_x  [NTOK*DD];       // residual stream, fp32
__device__ float g_qkv[NTOK*3*DD];     // fp32, read by attention

__device__ __half g_h_hi  [NTOK*384];
__device__ __half g_h_lo  [NTOK*384];
__device__ __half g_hn_hi [NTOK*DD];         // single-term consumers (qkv, fc1)
__device__ __half g_att_hi[NTOK*DD];
__device__ __half g_att_lo[NTOK*DD];
__device__ __half g_ffn_hi[NTOK*4*DD];
__device__ __half g_ffn_lo[NTOK*4*DD];

// transposed weights [N][K], single fp16 (round-to-nearest)
__device__ __half g_w2h  [DD*384];
__device__ __half g_qkvh [3*DD*DD];
__device__ __half g_woh  [DD*DD];
__device__ __half g_fc1h [4*DD*DD];
__device__ __half g_fc2h [DD*4*DD];

// ============================ helpers ========================================
__device__ __forceinline__ uint32_t smem_u32(const void* p) {
    uint32_t a;
    asm("{ .reg .u64 t; cvta.to.shared.u64 t, %1; cvt.u32.u64 %0, t; }" : "=r"(a) : "l"(p));
    return a;
}
__device__ __forceinline__ void split_f16(float v, __half& h, __half& l) {
    h = __float2half_rn(v);
    l = __float2half_rn(v - __half2float(h));
}
__device__ __forceinline__ uint32_t h2pack(__half a, __half b) {
    __half2 h; h.x = a; h.y = b;
    return *(uint32_t*)&h;
}
__device__ __forceinline__ void ldsm4(uint32_t* r, uint32_t addr) {
    asm volatile("ldmatrix.sync.aligned.m8n8.x4.shared.b16 {%0,%1,%2,%3}, [%4];"
        : "=r"(r[0]), "=r"(r[1]), "=r"(r[2]), "=r"(r[3]) : "r"(addr));
}
__device__ __forceinline__ void mma16816(float* c, const uint32_t* a, uint32_t b0, uint32_t b1) {
    asm volatile(
        "mma.sync.aligned.m16n8k16.row.col.f32.f16.f16.f32 "
        "{%0,%1,%2,%3}, {%4,%5,%6,%7}, {%8,%9}, {%0,%1,%2,%3};"
        : "+f"(c[0]), "+f"(c[1]), "+f"(c[2]), "+f"(c[3])
        : "r"(a[0]), "r"(a[1]), "r"(a[2]), "r"(a[3]), "r"(b0), "r"(b1));
}
__device__ __forceinline__ void cpa16(uint32_t dst, const void* src) {
    asm volatile("cp.async.cg.shared.global [%0], [%1], 16;" :: "r"(dst), "l"(src) : "memory");
}
#define CP_COMMIT() asm volatile("cp.async.commit_group;" ::: "memory")
#define CP_WAIT0()  asm volatile("cp.async.wait_group 0;" ::: "memory")

// ---------------- fused weight transpose (one launch, fp16 RN) --------------
__global__ void tsplit_all_k(
    const float* __restrict__ w2, const float* __restrict__ wqkv,
    const float* __restrict__ wo, const float* __restrict__ wfc1,
    const float* __restrict__ wfc2)
{
    int b = blockIdx.x;
    const float* W; __half* Th; int K, N, nbx;
    if (b < 288)       { W = w2;   Th = g_w2h;  K = 384;  N = 768;  nbx = 24; }
    else if (b < 2016) { b -= 288;  W = wqkv; Th = g_qkvh; K = 768;  N = 2304; nbx = 72; }
    else if (b < 2592) { b -= 2016; W = wo;   Th = g_woh;  K = 768;  N = 768;  nbx = 24; }
    else if (b < 4896) { b -= 2592; W = wfc1; Th = g_fc1h; K = 768;  N = 3072; nbx = 96; }
    else               { b -= 4896; W = wfc2; Th = g_fc2h; K = 3072; N = 768;  nbx = 24; }
    int nb = (b % nbx) * 32, kb = (b / nbx) * 32;

    __shared__ float t[32][33];
    int x = threadIdx.x, y = threadIdx.y;   // (32, 8)
#pragma unroll
    for (int i = 0; i < 32; i += 8)
        t[y + i][x] = W[(size_t)(kb + y + i) * N + nb + x];
    __syncthreads();
#pragma unroll
    for (int i = 0; i < 32; i += 8)
        Th[(size_t)(nb + y + i) * K + kb + x] = __float2half_rn(t[x][y + i]);
}

// ---------------- embed stage 1: h = relu(box @ w1), K=4 --------------------
__global__ void embed_h_k(const float* __restrict__ box, const float* __restrict__ w1)
{
    int idx = blockIdx.x * blockDim.x + threadIdx.x;
    if (idx >= NTOK * 384) return;
    int m = idx / 384, j = idx - m * 384;
    const float* bx = box + m * 4;
    float acc = bx[0] * w1[j] + bx[1] * w1[384 + j] + bx[2] * w1[768 + j] + bx[3] * w1[1152 + j];
    acc = fmaxf(acc, 0.0f);
    split_f16(acc, g_h_hi[idx], g_h_lo[idx]);
}

// ================= HMMA fp16 GEMM, cp.async double-buffered, KC=64 ==========
// C[M,N] = epi(A @ B^T). SPLIT=1: A = Ahi+Alo (2 MMA terms). SPLIT=0: A = Ahi.
// CTA tile TM x 128, 8 warps (2m x 4n). Rows 64 halves + 16B pad = 144B stride.
template<int EPI, int TM, int SPLIT>
__global__ void __launch_bounds__(256)
hgemm_k(const __half* __restrict__ Ahi, const __half* __restrict__ Alo,
        const __half* __restrict__ Bh16,
        const float* __restrict__ bias, const float* __restrict__ res,
        float* __restrict__ Cf, __half* __restrict__ Chi, __half* __restrict__ Clo,
        int M, int N, int K)
{
    extern __shared__ __align__(16) __half smbuf[];
    constexpr int MT = TM / 32;
    constexpr uint32_t offAh = 0;
    constexpr uint32_t offAl = (uint32_t)TM * 144;              // only if SPLIT
    constexpr uint32_t offB  = (uint32_t)TM * 144 * (1 + SPLIT);
    constexpr uint32_t STG_B = (uint32_t)(TM * (1 + SPLIT) + 128) * 144;

    const int tid = threadIdx.x;
    const int wid = tid >> 5, lane = tid & 31;
    const int wm = wid >> 2, wn = wid & 3;
    const int m0 = blockIdx.y * TM, n0 = blockIdx.x * 128;
    const uint32_t smb = smem_u32(smbuf);

    const int nch = K >> 6;

    auto load_stage = [&](int st, int kb) {
        uint32_t sb = smb + (uint32_t)st * STG_B;
#pragma unroll
        for (int s = tid; s < TM * 8; s += 256) {
            int row = s >> 3, seg = s & 7;
            uint32_t d = sb + (uint32_t)(row * 144 + seg * 16);
            size_t go = (size_t)(m0 + row) * K + kb + seg * 8;
            cpa16(d + offAh, Ahi + go);
            if (SPLIT) cpa16(d + offAl, Alo + go);
        }
#pragma unroll
        for (int s = tid; s < 1024; s += 256) {
            int row = s >> 3, seg = s & 7;
            uint32_t d = sb + (uint32_t)(row * 144 + seg * 16);
            size_t go = (size_t)(n0 + row) * K + kb + seg * 8;
            cpa16(d + offB, Bh16 + go);
        }
    };

    const uint32_t a_lo = (uint32_t)(lane & 15) * 144 + (uint32_t)(lane >> 4) * 16;
    const uint32_t a_wb = (uint32_t)(wm * (TM / 2)) * 144;
    const uint32_t b_wb = (uint32_t)(wn * 32) * 144;

    float c[MT][4][4] = {};

    load_stage(0, 0);
    CP_COMMIT();

    for (int ch = 0; ch < nch; ch++) {
        CP_WAIT0();
        __syncthreads();
        if (ch + 1 < nch) {
            load_stage((ch + 1) & 1, (ch + 1) << 6);
            CP_COMMIT();
        }
        uint32_t sb = smb + (uint32_t)(ch & 1) * STG_B;
#pragma unroll
        for (int ks = 0; ks < 4; ks++) {
            uint32_t koff = ks * 32;
            uint32_t ah[MT][4], al[MT][4], bh[2][4];
#pragma unroll
            for (int mt = 0; mt < MT; mt++) {
                uint32_t off = a_wb + (uint32_t)(mt * 16) * 144 + a_lo + koff;
                ldsm4(ah[mt], sb + offAh + off);
                if (SPLIT) ldsm4(al[mt], sb + offAl + off);
            }
#pragma unroll
            for (int p = 0; p < 2; p++) {
                uint32_t off = b_wb + (uint32_t)(p * 16) * 144 + a_lo + koff;
                ldsm4(bh[p], sb + offB + off);
            }
#pragma unroll
            for (int mt = 0; mt < MT; mt++) {
#pragma unroll
                for (int p = 0; p < 2; p++) {
#pragma unroll
                    for (int s = 0; s < 2; s++) {
                        int nt = p * 2 + s;
                        uint32_t b0 = bh[p][s], b1 = bh[p][s + 2];
                        mma16816(c[mt][nt], ah[mt], b0, b1);
                        if (SPLIT) mma16816(c[mt][nt], al[mt], b0, b1);
                    }
                }
            }
        }
        __syncthreads();
    }

    const int rbase = m0 + wm * (TM / 2) + (lane >> 2);
    const int cbase = n0 + wn * 32 + (lane & 3) * 2;
#pragma unroll
    for (int mt = 0; mt < MT; mt++) {
#pragma unroll
        for (int rr = 0; rr < 2; rr++) {
            int m = rbase + mt * 16 + rr * 8;
#pragma unroll
            for (int nt = 0; nt < 4; nt++) {
                int n = cbase + nt * 8;
                float v0 = c[mt][nt][rr * 2 + 0];
                float v1 = c[mt][nt][rr * 2 + 1];
                if (EPI == 1) {
                    const float* rp = res + (size_t)(m % LL) * N + n;
                    v0 = fmaxf(v0, 0.0f) + rp[0];
                    v1 = fmaxf(v1, 0.0f) + rp[1];
                    *(float2*)(Cf + (size_t)m * N + n) = make_float2(v0, v1);
                } else if (EPI == 2) {
                    const float* rp = res + (size_t)m * N + n;
                    v0 += bias[n] + rp[0];
                    v1 += bias[n + 1] + rp[1];
                    *(float2*)(Cf + (size_t)m * N + n) = make_float2(v0, v1);
                } else if (EPI == 3) {
                    v0 += bias[n];
                    v1 += bias[n + 1];
                    v0 = 0.5f * v0 * (1.0f + erff(v0 * 0.70710678118654752f));
                    v1 = 0.5f * v1 * (1.0f + erff(v1 * 0.70710678118654752f));
                    __half h0, l0, h1, l1;
                    split_f16(v0, h0, l0);
                    split_f16(v1, h1, l1);
                    *(__half2*)(Chi + (size_t)m * N + n) = __halves2half2(h0, h1);
                    *(__half2*)(Clo + (size_t)m * N + n) = __halves2half2(l0, l1);
                } else {
                    *(float2*)(Cf + (size_t)m * N + n) = make_float2(v0, v1);
                }
            }
        }
    }
}

// ================= HMMA attention: one block per (b,h), 160 threads =========
#define KSTR 72
#define VSTR 168
#define ATT_SMEM ((2*160*KSTR + 2*64*VSTR) * 2)   // 89088 bytes

__global__ void __launch_bounds__(160)
attn_k(const float* __restrict__ qkv, __half* __restrict__ Yhi, __half* __restrict__ Ylo)
{
    extern __shared__ __half smh[];
    __half* sKh = smh;
    __half* sKl = smh + 160 * KSTR;
    __half* sVh = smh + 2 * 160 * KSTR;
    __half* sVl = smh + 2 * 160 * KSTR + 64 * VSTR;

    const int bh = blockIdx.x;
    const int b = bh / NHH, h = bh - b * NHH;
    const int tid = threadIdx.x;
    const int wid = tid >> 5, lane = tid & 31;
    const int g = lane >> 2, t = lane & 3;

    for (int idx = tid; idx < 160 * 64; idx += 160) {
        int row = idx >> 6, col = idx & 63;
        size_t base = (size_t)(b * LL + row) * 2304 + h * 64 + col;
        float kv = qkv[base + 768];
        float vv = qkv[base + 1536];
        __half khh, kll; split_f16(kv, khh, kll);
        sKh[row * KSTR + col] = khh;
        sKl[row * KSTR + col] = kll;
        __half vhh, vll; split_f16(vv, vhh, vll);
        sVh[col * VSTR + row] = vhh;
        sVl[col * VSTR + row] = vll;
    }
    __syncthreads();

    const uint32_t kh_b = smem_u32(sKh), kl_b = smem_u32(sKl);
    const uint32_t vh_b = smem_u32(sVh), vl_b = smem_u32(sVl);
    const uint32_t lrow = (uint32_t)(lane & 15);
    const uint32_t lseg = (uint32_t)(lane >> 4) * 16;

#pragma unroll
    for (int mi = 0; mi < 2; mi++) {
        const int mt = wid * 2 + mi;
        const size_t qrow0 = (size_t)(b * LL + mt * 16 + g) * 2304 + h * 64;
        const size_t qrow1 = qrow0 + 8 * 2304;

        uint32_t qh[4][4], ql[4][4];
#pragma unroll
        for (int kt = 0; kt < 4; kt++) {
            int c0 = kt * 16 + 2 * t;
            float2 x0 = *(const float2*)(qkv + qrow0 + c0);
            float2 x1 = *(const float2*)(qkv + qrow1 + c0);
            float2 x2 = *(const float2*)(qkv + qrow0 + c0 + 8);
            float2 x3 = *(const float2*)(qkv + qrow1 + c0 + 8);
            float f[4][2] = {{x0.x * 0.125f, x0.y * 0.125f}, {x1.x * 0.125f, x1.y * 0.125f},
                             {x2.x * 0.125f, x2.y * 0.125f}, {x3.x * 0.125f, x3.y * 0.125f}};
#pragma unroll
            for (int a = 0; a < 4; a++) {
                __half h0, l0, h1, l1;
                split_f16(f[a][0], h0, l0);
                split_f16(f[a][1], h1, l1);
                qh[kt][a] = h2pack(h0, h1);
                ql[kt][a] = h2pack(l0, l1);
            }
        }

        float c[20][4];
#pragma unroll
        for (int nt = 0; nt < 20; nt++)
#pragma unroll
            for (int e = 0; e < 4; e++) c[nt][e] = 0.f;

        for (int n2 = 0; n2 < 10; n2++) {
            uint32_t roff = (uint32_t)(n2 * 16) * 144 + lrow * 144 + lseg;
#pragma unroll
            for (int kt = 0; kt < 4; kt++) {
                uint32_t kfh[4], kfl[4];
                ldsm4(kfh, kh_b + roff + kt * 32);
                ldsm4(kfl, kl_b + roff + kt * 32);
#pragma unroll
                for (int s = 0; s < 2; s++) {
                    float* cc = c[n2 * 2 + s];
                    mma16816(cc, qh[kt], kfh[s], kfh[s + 2]);
                    mma16816(cc, ql[kt], kfh[s], kfh[s + 2]);
                    mma16816(cc, qh[kt], kfl[s], kfl[s + 2]);
                }
            }
        }

        float m0 = -1e30f, m1 = -1e30f;
#pragma unroll
        for (int nt = 0; nt < 20; nt++) {
            m0 = fmaxf(m0, fmaxf(c[nt][0], c[nt][1]));
            m1 = fmaxf(m1, fmaxf(c[nt][2], c[nt][3]));
        }
#pragma unroll
        for (int off = 1; off <= 2; off <<= 1) {
            m0 = fmaxf(m0, __shfl_xor_sync(0xffffffffu, m0, off));
            m1 = fmaxf(m1, __shfl_xor_sync(0xffffffffu, m1, off));
        }
        float s0 = 0.f, s1 = 0.f;
#pragma unroll
        for (int nt = 0; nt < 20; nt++) {
            c[nt][0] = __expf(c[nt][0] - m0);
            c[nt][1] = __expf(c[nt][1] - m0);
            c[nt][2] = __expf(c[nt][2] - m1);
            c[nt][3] = __expf(c[nt][3] - m1);
            s0 += c[nt][0] + c[nt][1];
            s1 += c[nt][2] + c[nt][3];
        }
#pragma unroll
        for (int off = 1; off <= 2; off <<= 1) {
            s0 += __shfl_xor_sync(0xffffffffu, s0, off);
            s1 += __shfl_xor_sync(0xffffffffu, s1, off);
        }
        const float inv0 = 1.0f / s0, inv1 = 1.0f / s1;

        float o[8][4];
#pragma unroll
        for (int nt = 0; nt < 8; nt++)
#pragma unroll
            for (int e = 0; e < 4; e++) o[nt][e] = 0.f;

        for (int k2 = 0; k2 < 10; k2++) {
            uint32_t ph[4], pl[4];
            {
                const float* ca = c[2 * k2];
                const float* cb = c[2 * k2 + 1];
                __half ha, la, hb, lb;
                split_f16(ca[0], ha, la); split_f16(ca[1], hb, lb);
                ph[0] = h2pack(ha, hb); pl[0] = h2pack(la, lb);
                split_f16(ca[2], ha, la); split_f16(ca[3], hb, lb);
                ph[1] = h2pack(ha, hb); pl[1] = h2pack(la, lb);
                split_f16(cb[0], ha, la); split_f16(cb[1], hb, lb);
                ph[2] = h2pack(ha, hb); pl[2] = h2pack(la, lb);
                split_f16(cb[2], ha, la); split_f16(cb[3], hb, lb);
                ph[3] = h2pack(ha, hb); pl[3] = h2pack(la, lb);
            }
#pragma unroll
            for (int n2v = 0; n2v < 4; n2v++) {
                uint32_t roff = (uint32_t)(n2v * 16) * 336 + lrow * 336 + lseg + k2 * 32;
                uint32_t vfh[4], vfl[4];
                ldsm4(vfh, vh_b + roff);
                ldsm4(vfl, vl_b + roff);
#pragma unroll
                for (int s = 0; s < 2; s++) {
                    float* oo = o[n2v * 2 + s];
                    mma16816(oo, ph, vfh[s], vfh[s + 2]);
                    mma16816(oo, pl, vfh[s], vfh[s + 2]);
                    mma16816(oo, ph, vfl[s], vfl[s + 2]);
                }
            }
        }

        const size_t row0 = (size_t)(b * LL + mt * 16 + g) * DD + h * 64;
        const size_t row1 = row0 + (size_t)8 * DD;
#pragma unroll
        for (int nt = 0; nt < 8; nt++) {
            int col = nt * 8 + 2 * t;
            float v0 = o[nt][0] * inv0, v1 = o[nt][1] * inv0;
            float v2 = o[nt][2] * inv1, v3 = o[nt][3] * inv1;
            __half h0, l0, h1, l1;
            split_f16(v0, h0, l0); split_f16(v1, h1, l1);
            *(__half2*)(Yhi + row0 + col) = __halves2half2(h0, h1);
            *(__half2*)(Ylo + row0 + col) = __halves2half2(l0, l1);
            split_f16(v2, h0, l0); split_f16(v3, h1, l1);
            *(__half2*)(Yhi + row1 + col) = __halves2half2(h0, h1);
            *(__half2*)(Ylo + row1 + col) = __halves2half2(l0, l1);
        }
    }
}

// ---------------- layernorm: one block per row, fp16-hi output only ---------
__global__ void ln_k(const float* __restrict__ X, const float* __restrict__ g,
                     const float* __restrict__ b, __half* __restrict__ Yhi)
{
    int row = blockIdx.x;
    const float* x = X + (size_t)row * DD;
    int tid = threadIdx.x;
    float v[3];
    float s = 0.f, sq = 0.f;
#pragma unroll
    for (int r = 0; r < 3; r++) {
        v[r] = x[tid + r * 256];
        s += v[r];
        sq += v[r] * v[r];
    }
    __shared__ float red0[8], red1[8];
#pragma unroll
    for (int off = 16; off; off >>= 1) {
        s += __shfl_down_sync(0xffffffffu, s, off);
        sq += __shfl_down_sync(0xffffffffu, sq, off);
    }
    if ((tid & 31) == 0) { red0[tid >> 5] = s; red1[tid >> 5] = sq; }
    __syncthreads();
    s = 0.f; sq = 0.f;
#pragma unroll
    for (int i = 0; i < 8; i++) { s += red0[i]; sq += red1[i]; }
    float mean = s * (1.0f / DD);
    float var = sq * (1.0f / DD) - mean * mean;
    float rstd = rsqrtf(var + 1e-5f);
#pragma unroll
    for (int r = 0; r < 3; r++) {
        int c = tid + r * 256;
        float y = (v[r] - mean) * rstd * g[c] + b[c];
        Yhi[(size_t)row * DD + c] = __float2half_rn(y);
    }
}

// ---------------- box-mask scatter + temporal mean ---------------------------
__global__ void grid_k(const float* __restrict__ box, float* __restrict__ out)
{
    int blk = blockIdx.x;
    int w = blk % GW;
    int hh = (blk / GW) % GH;
    int tg = (blk / (GW * GH)) & 7;
    int b = blk / (GW * GH * 8);
    int tid = threadIdx.x;

    __shared__ float flg[20];
    if (tid < 20) {
        int t = tg * 2 + tid / 10;
        int o = tid % 10;
        const float* bx = box + (size_t)((b * TT + t) * OO + o) * 4;
        float x1 = fminf(bx[0], bx[2]), x2 = fmaxf(bx[0], bx[2]);
        float y1 = fminf(bx[1], bx[3]), y2 = fmaxf(bx[1], bx[3]);
        float cy = (hh + 0.5f) / 14.0f;
        float cx = (w + 0.5f) / 14.0f;
        flg[tid] = (cy >= y1 && cy <= y2 && cx >= x1 && cx <= x2) ? 1.0f : 0.0f;
    }
    __syncthreads();

    float a0 = 0.f, a1 = 0.f, a2 = 0.f;
#pragma unroll
    for (int e = 0; e < 20; e++) {
        if (flg[e] > 0.f) {
            const float* f = g_x + (size_t)(b * LL + (tg * 2 + e / 10) * OO + (e % 10)) * DD + tid;
            a0 += f[0];
            a1 += f[256];
            a2 += f[512];
        }
    }
    size_t ob = (size_t)blk * DD + tid;
    out[ob]       = 0.5f * a0;
    out[ob + 256] = 0.5f * a1;
    out[ob + 512] = 0.5f * a2;
}

// ---------------- launch ------------------------------------------------------
extern "C" void kernel_launch(void* const* d_in, const int* in_sizes, int n_in,
                              void* d_out, int out_size)
{
    const float* box  = (const float*)d_in[0];
    const float* cat  = (const float*)d_in[1];
    const float* w1   = (const float*)d_in[2];
    const float* w2   = (const float*)d_in[3];
    const float* ln1g = (const float*)d_in[4];
    const float* ln1b = (const float*)d_in[5];
    const float* wqkv = (const float*)d_in[6];
    const float* wo   = (const float*)d_in[7];
    const float* bo   = (const float*)d_in[8];
    const float* ln2g = (const float*)d_in[9];
    const float* ln2b = (const float*)d_in[10];
    const float* wfc1 = (const float*)d_in[11];
    const float* bfc1 = (const float*)d_in[12];
    const float* wfc2 = (const float*)d_in[13];
    const float* bfc2 = (const float*)d_in[14];
    float* out = (float*)d_out;

    float *gx, *gqkv;
    __half *ghh, *ghl, *ghnh, *gatth, *gattl, *gffnh, *gffnl;
    __half *w2h, *qkh, *woh, *f1h, *f2h;
    cudaGetSymbolAddress((void**)&gx,    g_x);
    cudaGetSymbolAddress((void**)&gqkv,  g_qkv);
    cudaGetSymbolAddress((void**)&ghh,   g_h_hi);
    cudaGetSymbolAddress((void**)&ghl,   g_h_lo);
    cudaGetSymbolAddress((void**)&ghnh,  g_hn_hi);
    cudaGetSymbolAddress((void**)&gatth, g_att_hi);
    cudaGetSymbolAddress((void**)&gattl, g_att_lo);
    cudaGetSymbolAddress((void**)&gffnh, g_ffn_hi);
    cudaGetSymbolAddress((void**)&gffnl, g_ffn_lo);
    cudaGetSymbolAddress((void**)&w2h,   g_w2h);
    cudaGetSymbolAddress((void**)&qkh,   g_qkvh);
    cudaGetSymbolAddress((void**)&woh,   g_woh);
    cudaGetSymbolAddress((void**)&f1h,   g_fc1h);
    cudaGetSymbolAddress((void**)&f2h,   g_fc2h);

    cudaFuncSetAttribute(attn_k, cudaFuncAttributeMaxDynamicSharedMemorySize, ATT_SMEM);

    // smem per config: (TM*(1+SPLIT)+128)*144*2
    const int sm_s1_64  = (64 * 2 + 128) * 144 * 2;   // 73728
    const int sm_s0_128 = (128 + 128) * 144 * 2;      // 73728
    cudaFuncSetAttribute((const void*)hgemm_k<1, 64, 1>,  cudaFuncAttributeMaxDynamicSharedMemorySize, sm_s1_64);
    cudaFuncSetAttribute((const void*)hgemm_k<2, 64, 1>,  cudaFuncAttributeMaxDynamicSharedMemorySize, sm_s1_64);
    cudaFuncSetAttribute((const void*)hgemm_k<0, 128, 0>, cudaFuncAttributeMaxDynamicSharedMemorySize, sm_s0_128);
    cudaFuncSetAttribute((const void*)hgemm_k<3, 128, 0>, cudaFuncAttributeMaxDynamicSharedMemorySize, sm_s0_128);

    tsplit_all_k<<<7200, dim3(32, 8)>>>(w2, wqkv, wo, wfc1, wfc2);

    embed_h_k<<<(NTOK * 384 + 255) / 256, 256>>>(box, w1);

    // 2) x = relu(h @ w2) + cat   (2-term A)
    hgemm_k<1, 64, 1><<<dim3(DD / 128, NTOK / 64), 256, sm_s1_64>>>(
        ghh, ghl, w2h, nullptr, cat, gx, nullptr, nullptr, NTOK, DD, 384);

    ln_k<<<NTOK, 256>>>(gx, ln1g, ln1b, ghnh);

    // 4) qkv = hn @ wqkv   (single-term A)
    hgemm_k<0, 128, 0><<<dim3(3 * DD / 128, NTOK / 128), 256, sm_s0_128>>>(
        ghnh, nullptr, qkh, nullptr, nullptr, gqkv, nullptr, nullptr, NTOK, 3 * DD, DD);

    attn_k<<<BB * NHH, 160, ATT_SMEM>>>(gqkv, gatth, gattl);

    // 6) x = x + att @ wo + bo   (2-term A)
    hgemm_k<2, 64, 1><<<dim3(DD / 128, NTOK / 64), 256, sm_s1_64>>>(
        gatth, gattl, woh, bo, gx, gx, nullptr, nullptr, NTOK, DD, DD);

    ln_k<<<NTOK, 256>>>(gx, ln2g, ln2b, ghnh);

    // 8) ffn = gelu(hn @ wfc1 + bfc1)   (single-term A) -> split fp16
    hgemm_k<3, 128, 0><<<dim3(4 * DD / 128, NTOK / 128), 256, sm_s0_128>>>(
        ghnh, nullptr, f1h, bfc1, nullptr, nullptr, gffnh, gffnl, NTOK, 4 * DD, DD);

    // 9) x = x + ffn @ wfc2 + bfc2   (2-term A)
    hgemm_k<2, 64, 1><<<dim3(DD / 128, NTOK / 64), 256, sm_s1_64>>>(
        gffnh, gffnl, f2h, bfc2, gx, gx, nullptr, nullptr, NTOK, DD, 4 * DD);

    grid_k<<<BB * 8 * GH * GW, 256>>>(box, out);
}

// round 8
// speedup vs baseline: 4.1219x; 1.2068x over previous
#include <cuda_runtime.h>
#include <cuda_fp16.h>
#include <math.h>
#include <stdint.h>

#define BB   16
#define TT   16
#define OO   10
#define LL   160      // T*O
#define DD   768
#define NHH  12
#define DHH  64
#define GH   14
#define GW   14
#define NTOK (BB*LL)  // 2560

// ---------------- scratch (device globals; no runtime alloc allowed) --------
__device__ float g_x  [NTOK*DD];       // residual stream, fp32
__device__ float g_qkv[NTOK*3*DD];     // fp32, read by attention

__device__ __half g_h_hi  [NTOK*384];
__device__ __half g_hn_hi [NTOK*DD];
__device__ __half g_att_hi[NTOK*DD];
__device__ __half g_ffn_hi[NTOK*4*DD];

// transposed weights [N][K], single fp16 (round-to-nearest)
__device__ __half g_w2h  [DD*384];
__device__ __half g_qkvh [3*DD*DD];
__device__ __half g_woh  [DD*DD];
__device__ __half g_fc1h [4*DD*DD];
__device__ __half g_fc2h [DD*4*DD];

// ============================ helpers ========================================
__device__ __forceinline__ uint32_t smem_u32(const void* p) {
    uint32_t a;
    asm("{ .reg .u64 t; cvta.to.shared.u64 t, %1; cvt.u32.u64 %0, t; }" : "=r"(a) : "l"(p));
    return a;
}
__device__ __forceinline__ void split_f16(float v, __half& h, __half& l) {
    h = __float2half_rn(v);
    l = __float2half_rn(v - __half2float(h));
}
__device__ __forceinline__ uint32_t h2pack(__half a, __half b) {
    __half2 h; h.x = a; h.y = b;
    return *(uint32_t*)&h;
}
__device__ __forceinline__ void ldsm4(uint32_t* r, uint32_t addr) {
    asm volatile("ldmatrix.sync.aligned.m8n8.x4.shared.b16 {%0,%1,%2,%3}, [%4];"
        : "=r"(r[0]), "=r"(r[1]), "=r"(r[2]), "=r"(r[3]) : "r"(addr));
}
__device__ __forceinline__ void mma16816(float* c, const uint32_t* a, uint32_t b0, uint32_t b1) {
    asm volatile(
        "mma.sync.aligned.m16n8k16.row.col.f32.f16.f16.f32 "
        "{%0,%1,%2,%3}, {%4,%5,%6,%7}, {%8,%9}, {%0,%1,%2,%3};"
        : "+f"(c[0]), "+f"(c[1]), "+f"(c[2]), "+f"(c[3])
        : "r"(a[0]), "r"(a[1]), "r"(a[2]), "r"(a[3]), "r"(b0), "r"(b1));
}
__device__ __forceinline__ void cpa16(uint32_t dst, const void* src) {
    asm volatile("cp.async.cg.shared.global [%0], [%1], 16;" :: "r"(dst), "l"(src) : "memory");
}
#define CP_COMMIT() asm volatile("cp.async.commit_group;" ::: "memory")
#define CP_WAIT0()  asm volatile("cp.async.wait_group 0;" ::: "memory")

// ---------------- fused weight transpose (one launch, fp16 RN) --------------
__global__ void tsplit_all_k(
    const float* __restrict__ w2, const float* __restrict__ wqkv,
    const float* __restrict__ wo, const float* __restrict__ wfc1,
    const float* __restrict__ wfc2)
{
    int b = blockIdx.x;
    const float* W; __half* Th; int K, N, nbx;
    if (b < 288)       { W = w2;   Th = g_w2h;  K = 384;  N = 768;  nbx = 24; }
    else if (b < 2016) { b -= 288;  W = wqkv; Th = g_qkvh; K = 768;  N = 2304; nbx = 72; }
    else if (b < 2592) { b -= 2016; W = wo;   Th = g_woh;  K = 768;  N = 768;  nbx = 24; }
    else if (b < 4896) { b -= 2592; W = wfc1; Th = g_fc1h; K = 768;  N = 3072; nbx = 96; }
    else               { b -= 4896; W = wfc2; Th = g_fc2h; K = 3072; N = 768;  nbx = 24; }
    int nb = (b % nbx) * 32, kb = (b / nbx) * 32;

    __shared__ float t[32][33];
    int x = threadIdx.x, y = threadIdx.y;   // (32, 8)
#pragma unroll
    for (int i = 0; i < 32; i += 8)
        t[y + i][x] = W[(size_t)(kb + y + i) * N + nb + x];
    __syncthreads();
#pragma unroll
    for (int i = 0; i < 32; i += 8)
        Th[(size_t)(nb + y + i) * K + kb + x] = __float2half_rn(t[x][y + i]);
}

// ---------------- embed stage 1: h = relu(box @ w1), K=4 --------------------
__global__ void embed_h_k(const float* __restrict__ box, const float* __restrict__ w1)
{
    int idx = blockIdx.x * blockDim.x + threadIdx.x;
    if (idx >= NTOK * 384) return;
    int m = idx / 384, j = idx - m * 384;
    const float* bx = box + m * 4;
    float acc = bx[0] * w1[j] + bx[1] * w1[384 + j] + bx[2] * w1[768 + j] + bx[3] * w1[1152 + j];
    g_h_hi[idx] = __float2half_rn(fmaxf(acc, 0.0f));
}

// ================= HMMA fp16 GEMM, cp.async double-buffered, KC=64 ==========
// C[M,N] = epi(A @ B^T). A [M][K] fp16, B [N][K] fp16.
// CTA tile TM x 128, 8 warps (2m x 4n). Rows 64 halves + 16B pad = 144B stride.
// EPI: 0 plain fp32; 1 relu + res[(m%LL)*N+n]; 2 +bias+res[m*N+n]; 3 +bias, gelu -> fp16
template<int EPI, int TM>
__global__ void __launch_bounds__(256)
hgemm_k(const __half* __restrict__ Ah, const __half* __restrict__ Bh16,
        const float* __restrict__ bias, const float* __restrict__ res,
        float* __restrict__ Cf, __half* __restrict__ Chi,
        int M, int N, int K)
{
    extern __shared__ __align__(16) __half smbuf[];
    constexpr int MT = TM / 32;
    constexpr uint32_t offB  = (uint32_t)TM * 144;
    constexpr uint32_t STG_B = (uint32_t)(TM + 128) * 144;

    const int tid = threadIdx.x;
    const int wid = tid >> 5, lane = tid & 31;
    const int wm = wid >> 2, wn = wid & 3;
    const int m0 = blockIdx.y * TM, n0 = blockIdx.x * 128;
    const uint32_t smb = smem_u32(smbuf);

    const int nch = K >> 6;

    auto load_stage = [&](int st, int kb) {
        uint32_t sb = smb + (uint32_t)st * STG_B;
#pragma unroll
        for (int s = tid; s < TM * 8; s += 256) {
            int row = s >> 3, seg = s & 7;
            uint32_t d = sb + (uint32_t)(row * 144 + seg * 16);
            cpa16(d, Ah + (size_t)(m0 + row) * K + kb + seg * 8);
        }
#pragma unroll
        for (int s = tid; s < 1024; s += 256) {
            int row = s >> 3, seg = s & 7;
            uint32_t d = sb + (uint32_t)(row * 144 + seg * 16);
            cpa16(d + offB, Bh16 + (size_t)(n0 + row) * K + kb + seg * 8);
        }
    };

    const uint32_t a_lo = (uint32_t)(lane & 15) * 144 + (uint32_t)(lane >> 4) * 16;
    const uint32_t a_wb = (uint32_t)(wm * (TM / 2)) * 144;
    const uint32_t b_wb = (uint32_t)(wn * 32) * 144;

    float c[MT][4][4] = {};

    load_stage(0, 0);
    CP_COMMIT();

    for (int ch = 0; ch < nch; ch++) {
        CP_WAIT0();
        __syncthreads();
        if (ch + 1 < nch) {
            load_stage((ch + 1) & 1, (ch + 1) << 6);
            CP_COMMIT();
        }
        uint32_t sb = smb + (uint32_t)(ch & 1) * STG_B;
#pragma unroll
        for (int ks = 0; ks < 4; ks++) {
            uint32_t koff = ks * 32;
            uint32_t ah[MT][4], bh[2][4];
#pragma unroll
            for (int mt = 0; mt < MT; mt++) {
                uint32_t off = a_wb + (uint32_t)(mt * 16) * 144 + a_lo + koff;
                ldsm4(ah[mt], sb + off);
            }
#pragma unroll
            for (int p = 0; p < 2; p++) {
                uint32_t off = b_wb + (uint32_t)(p * 16) * 144 + a_lo + koff;
                ldsm4(bh[p], sb + offB + off);
            }
#pragma unroll
            for (int mt = 0; mt < MT; mt++) {
#pragma unroll
                for (int p = 0; p < 2; p++) {
#pragma unroll
                    for (int s = 0; s < 2; s++) {
                        int nt = p * 2 + s;
                        mma16816(c[mt][nt], ah[mt], bh[p][s], bh[p][s + 2]);
                    }
                }
            }
        }
        __syncthreads();
    }

    const int rbase = m0 + wm * (TM / 2) + (lane >> 2);
    const int cbase = n0 + wn * 32 + (lane & 3) * 2;
#pragma unroll
    for (int mt = 0; mt < MT; mt++) {
#pragma unroll
        for (int rr = 0; rr < 2; rr++) {
            int m = rbase + mt * 16 + rr * 8;
#pragma unroll
            for (int nt = 0; nt < 4; nt++) {
                int n = cbase + nt * 8;
                float v0 = c[mt][nt][rr * 2 + 0];
                float v1 = c[mt][nt][rr * 2 + 1];
                if (EPI == 1) {
                    const float* rp = res + (size_t)(m % LL) * N + n;
                    v0 = fmaxf(v0, 0.0f) + rp[0];
                    v1 = fmaxf(v1, 0.0f) + rp[1];
                    *(float2*)(Cf + (size_t)m * N + n) = make_float2(v0, v1);
                } else if (EPI == 2) {
                    const float* rp = res + (size_t)m * N + n;
                    v0 += bias[n] + rp[0];
                    v1 += bias[n + 1] + rp[1];
                    *(float2*)(Cf + (size_t)m * N + n) = make_float2(v0, v1);
                } else if (EPI == 3) {
                    v0 += bias[n];
                    v1 += bias[n + 1];
                    v0 = 0.5f * v0 * (1.0f + erff(v0 * 0.70710678118654752f));
                    v1 = 0.5f * v1 * (1.0f + erff(v1 * 0.70710678118654752f));
                    *(__half2*)(Chi + (size_t)m * N + n) =
                        __halves2half2(__float2half_rn(v0), __float2half_rn(v1));
                } else {
                    *(float2*)(Cf + (size_t)m * N + n) = make_float2(v0, v1);
                }
            }
        }
    }
}

// ================= HMMA attention: one block per (b,h), 160 threads =========
// internal 3-term split: error-neutral vs fp32; output single fp16 (consumer is single-term)
#define KSTR 72
#define VSTR 168
#define ATT_SMEM ((2*160*KSTR + 2*64*VSTR) * 2)   // 89088 bytes

__global__ void __launch_bounds__(160)
attn_k(const float* __restrict__ qkv, __half* __restrict__ Yhi)
{
    extern __shared__ __half smh[];
    __half* sKh = smh;
    __half* sKl = smh + 160 * KSTR;
    __half* sVh = smh + 2 * 160 * KSTR;
    __half* sVl = smh + 2 * 160 * KSTR + 64 * VSTR;

    const int bh = blockIdx.x;
    const int b = bh / NHH, h = bh - b * NHH;
    const int tid = threadIdx.x;
    const int wid = tid >> 5, lane = tid & 31;
    const int g = lane >> 2, t = lane & 3;

    for (int idx = tid; idx < 160 * 64; idx += 160) {
        int row = idx >> 6, col = idx & 63;
        size_t base = (size_t)(b * LL + row) * 2304 + h * 64 + col;
        float kv = qkv[base + 768];
        float vv = qkv[base + 1536];
        __half khh, kll; split_f16(kv, khh, kll);
        sKh[row * KSTR + col] = khh;
        sKl[row * KSTR + col] = kll;
        __half vhh, vll; split_f16(vv, vhh, vll);
        sVh[col * VSTR + row] = vhh;
        sVl[col * VSTR + row] = vll;
    }
    __syncthreads();

    const uint32_t kh_b = smem_u32(sKh), kl_b = smem_u32(sKl);
    const uint32_t vh_b = smem_u32(sVh), vl_b = smem_u32(sVl);
    const uint32_t lrow = (uint32_t)(lane & 15);
    const uint32_t lseg = (uint32_t)(lane >> 4) * 16;

#pragma unroll
    for (int mi = 0; mi < 2; mi++) {
        const int mt = wid * 2 + mi;
        const size_t qrow0 = (size_t)(b * LL + mt * 16 + g) * 2304 + h * 64;
        const size_t qrow1 = qrow0 + 8 * 2304;

        uint32_t qh[4][4], ql[4][4];
#pragma unroll
        for (int kt = 0; kt < 4; kt++) {
            int c0 = kt * 16 + 2 * t;
            float2 x0 = *(const float2*)(qkv + qrow0 + c0);
            float2 x1 = *(const float2*)(qkv + qrow1 + c0);
            float2 x2 = *(const float2*)(qkv + qrow0 + c0 + 8);
            float2 x3 = *(const float2*)(qkv + qrow1 + c0 + 8);
            float f[4][2] = {{x0.x * 0.125f, x0.y * 0.125f}, {x1.x * 0.125f, x1.y * 0.125f},
                             {x2.x * 0.125f, x2.y * 0.125f}, {x3.x * 0.125f, x3.y * 0.125f}};
#pragma unroll
            for (int a = 0; a < 4; a++) {
                __half h0, l0, h1, l1;
                split_f16(f[a][0], h0, l0);
                split_f16(f[a][1], h1, l1);
                qh[kt][a] = h2pack(h0, h1);
                ql[kt][a] = h2pack(l0, l1);
            }
        }

        float c[20][4];
#pragma unroll
        for (int nt = 0; nt < 20; nt++)
#pragma unroll
            for (int e = 0; e < 4; e++) c[nt][e] = 0.f;

        for (int n2 = 0; n2 < 10; n2++) {
            uint32_t roff = (uint32_t)(n2 * 16) * 144 + lrow * 144 + lseg;
#pragma unroll
            for (int kt = 0; kt < 4; kt++) {
                uint32_t kfh[4], kfl[4];
                ldsm4(kfh, kh_b + roff + kt * 32);
                ldsm4(kfl, kl_b + roff + kt * 32);
#pragma unroll
                for (int s = 0; s < 2; s++) {
                    float* cc = c[n2 * 2 + s];
                    mma16816(cc, qh[kt], kfh[s], kfh[s + 2]);
                    mma16816(cc, ql[kt], kfh[s], kfh[s + 2]);
                    mma16816(cc, qh[kt], kfl[s], kfl[s + 2]);
                }
            }
        }

        float m0 = -1e30f, m1 = -1e30f;
#pragma unroll
        for (int nt = 0; nt < 20; nt++) {
            m0 = fmaxf(m0, fmaxf(c[nt][0], c[nt][1]));
            m1 = fmaxf(m1, fmaxf(c[nt][2], c[nt][3]));
        }
#pragma unroll
        for (int off = 1; off <= 2; off <<= 1) {
            m0 = fmaxf(m0, __shfl_xor_sync(0xffffffffu, m0, off));
            m1 = fmaxf(m1, __shfl_xor_sync(0xffffffffu, m1, off));
        }
        float s0 = 0.f, s1 = 0.f;
#pragma unroll
        for (int nt = 0; nt < 20; nt++) {
            c[nt][0] = __expf(c[nt][0] - m0);
            c[nt][1] = __expf(c[nt][1] - m0);
            c[nt][2] = __expf(c[nt][2] - m1);
            c[nt][3] = __expf(c[nt][3] - m1);
            s0 += c[nt][0] + c[nt][1];
            s1 += c[nt][2] + c[nt][3];
        }
#pragma unroll
        for (int off = 1; off <= 2; off <<= 1) {
            s0 += __shfl_xor_sync(0xffffffffu, s0, off);
            s1 += __shfl_xor_sync(0xffffffffu, s1, off);
        }
        const float inv0 = 1.0f / s0, inv1 = 1.0f / s1;

        float o[8][4];
#pragma unroll
        for (int nt = 0; nt < 8; nt++)
#pragma unroll
            for (int e = 0; e < 4; e++) o[nt][e] = 0.f;

        for (int k2 = 0; k2 < 10; k2++) {
            uint32_t ph[4], pl[4];
            {
                const float* ca = c[2 * k2];
                const float* cb = c[2 * k2 + 1];
                __half ha, la, hb, lb;
                split_f16(ca[0], ha, la); split_f16(ca[1], hb, lb);
                ph[0] = h2pack(ha, hb); pl[0] = h2pack(la, lb);
                split_f16(ca[2], ha, la); split_f16(ca[3], hb, lb);
                ph[1] = h2pack(ha, hb); pl[1] = h2pack(la, lb);
                split_f16(cb[0], ha, la); split_f16(cb[1], hb, lb);
                ph[2] = h2pack(ha, hb); pl[2] = h2pack(la, lb);
                split_f16(cb[2], ha, la); split_f16(cb[3], hb, lb);
                ph[3] = h2pack(ha, hb); pl[3] = h2pack(la, lb);
            }
#pragma unroll
            for (int n2v = 0; n2v < 4; n2v++) {
                uint32_t roff = (uint32_t)(n2v * 16) * 336 + lrow * 336 + lseg + k2 * 32;
                uint32_t vfh[4], vfl[4];
                ldsm4(vfh, vh_b + roff);
                ldsm4(vfl, vl_b + roff);
#pragma unroll
                for (int s = 0; s < 2; s++) {
                    float* oo = o[n2v * 2 + s];
                    mma16816(oo, ph, vfh[s], vfh[s + 2]);
                    mma16816(oo, pl, vfh[s], vfh[s + 2]);
                    mma16816(oo, ph, vfl[s], vfl[s + 2]);
                }
            }
        }

        const size_t row0 = (size_t)(b * LL + mt * 16 + g) * DD + h * 64;
        const size_t row1 = row0 + (size_t)8 * DD;
#pragma unroll
        for (int nt = 0; nt < 8; nt++) {
            int col = nt * 8 + 2 * t;
            *(__half2*)(Yhi + row0 + col) =
                __halves2half2(__float2half_rn(o[nt][0] * inv0), __float2half_rn(o[nt][1] * inv0));
            *(__half2*)(Yhi + row1 + col) =
                __halves2half2(__float2half_rn(o[nt][2] * inv1), __float2half_rn(o[nt][3] * inv1));
        }
    }
}

// ---------------- layernorm: one block per row, fp16 output -----------------
__global__ void ln_k(const float* __restrict__ X, const float* __restrict__ g,
                     const float* __restrict__ b, __half* __restrict__ Yhi)
{
    int row = blockIdx.x;
    const float* x = X + (size_t)row * DD;
    int tid = threadIdx.x;
    float v[3];
    float s = 0.f, sq = 0.f;
#pragma unroll
    for (int r = 0; r < 3; r++) {
        v[r] = x[tid + r * 256];
        s += v[r];
        sq += v[r] * v[r];
    }
    __shared__ float red0[8], red1[8];
#pragma unroll
    for (int off = 16; off; off >>= 1) {
        s += __shfl_down_sync(0xffffffffu, s, off);
        sq += __shfl_down_sync(0xffffffffu, sq, off);
    }
    if ((tid & 31) == 0) { red0[tid >> 5] = s; red1[tid >> 5] = sq; }
    __syncthreads();
    s = 0.f; sq = 0.f;
#pragma unroll
    for (int i = 0; i < 8; i++) { s += red0[i]; sq += red1[i]; }
    float mean = s * (1.0f / DD);
    float var = sq * (1.0f / DD) - mean * mean;
    float rstd = rsqrtf(var + 1e-5f);
#pragma unroll
    for (int r = 0; r < 3; r++) {
        int c = tid + r * 256;
        float y = (v[r] - mean) * rstd * g[c] + b[c];
        Yhi[(size_t)row * DD + c] = __float2half_rn(y);
    }
}

// ---------------- box-mask scatter + temporal mean ---------------------------
__global__ void grid_k(const float* __restrict__ box, float* __restrict__ out)
{
    int blk = blockIdx.x;
    int w = blk % GW;
    int hh = (blk / GW) % GH;
    int tg = (blk / (GW * GH)) & 7;
    int b = blk / (GW * GH * 8);
    int tid = threadIdx.x;

    __shared__ float flg[20];
    if (tid < 20) {
        int t = tg * 2 + tid / 10;
        int o = tid % 10;
        const float* bx = box + (size_t)((b * TT + t) * OO + o) * 4;
        float x1 = fminf(bx[0], bx[2]), x2 = fmaxf(bx[0], bx[2]);
        float y1 = fminf(bx[1], bx[3]), y2 = fmaxf(bx[1], bx[3]);
        float cy = (hh + 0.5f) / 14.0f;
        float cx = (w + 0.5f) / 14.0f;
        flg[tid] = (cy >= y1 && cy <= y2 && cx >= x1 && cx <= x2) ? 1.0f : 0.0f;
    }
    __syncthreads();

    float a0 = 0.f, a1 = 0.f, a2 = 0.f;
#pragma unroll
    for (int e = 0; e < 20; e++) {
        if (flg[e] > 0.f) {
            const float* f = g_x + (size_t)(b * LL + (tg * 2 + e / 10) * OO + (e % 10)) * DD + tid;
            a0 += f[0];
            a1 += f[256];
            a2 += f[512];
        }
    }
    size_t ob = (size_t)blk * DD + tid;
    out[ob]       = 0.5f * a0;
    out[ob + 256] = 0.5f * a1;
    out[ob + 512] = 0.5f * a2;
}

// ---------------- launch ------------------------------------------------------
extern "C" void kernel_launch(void* const* d_in, const int* in_sizes, int n_in,
                              void* d_out, int out_size)
{
    const float* box  = (const float*)d_in[0];
    const float* cat  = (const float*)d_in[1];
    const float* w1   = (const float*)d_in[2];
    const float* w2   = (const float*)d_in[3];
    const float* ln1g = (const float*)d_in[4];
    const float* ln1b = (const float*)d_in[5];
    const float* wqkv = (const float*)d_in[6];
    const float* wo   = (const float*)d_in[7];
    const float* bo   = (const float*)d_in[8];
    const float* ln2g = (const float*)d_in[9];
    const float* ln2b = (const float*)d_in[10];
    const float* wfc1 = (const float*)d_in[11];
    const float* bfc1 = (const float*)d_in[12];
    const float* wfc2 = (const float*)d_in[13];
    const float* bfc2 = (const float*)d_in[14];
    float* out = (float*)d_out;

    float *gx, *gqkv;
    __half *ghh, *ghnh, *gatth, *gffnh;
    __half *w2h, *qkh, *woh, *f1h, *f2h;
    cudaGetSymbolAddress((void**)&gx,    g_x);
    cudaGetSymbolAddress((void**)&gqkv,  g_qkv);
    cudaGetSymbolAddress((void**)&ghh,   g_h_hi);
    cudaGetSymbolAddress((void**)&ghnh,  g_hn_hi);
    cudaGetSymbolAddress((void**)&gatth, g_att_hi);
    cudaGetSymbolAddress((void**)&gffnh, g_ffn_hi);
    cudaGetSymbolAddress((void**)&w2h,   g_w2h);
    cudaGetSymbolAddress((void**)&qkh,   g_qkvh);
    cudaGetSymbolAddress((void**)&woh,   g_woh);
    cudaGetSymbolAddress((void**)&f1h,   g_fc1h);
    cudaGetSymbolAddress((void**)&f2h,   g_fc2h);

    cudaFuncSetAttribute(attn_k, cudaFuncAttributeMaxDynamicSharedMemorySize, ATT_SMEM);

    // smem per stage-pair: (TM+128)*144*2
    const int sm_64  = (64 + 128) * 144 * 2;    // 55296
    const int sm_128 = (128 + 128) * 144 * 2;   // 73728
    cudaFuncSetAttribute((const void*)hgemm_k<1, 64>,  cudaFuncAttributeMaxDynamicSharedMemorySize, sm_64);
    cudaFuncSetAttribute((const void*)hgemm_k<2, 64>,  cudaFuncAttributeMaxDynamicSharedMemorySize, sm_64);
    cudaFuncSetAttribute((const void*)hgemm_k<0, 128>, cudaFuncAttributeMaxDynamicSharedMemorySize, sm_128);
    cudaFuncSetAttribute((const void*)hgemm_k<3, 128>, cudaFuncAttributeMaxDynamicSharedMemorySize, sm_128);

    tsplit_all_k<<<7200, dim3(32, 8)>>>(w2, wqkv, wo, wfc1, wfc2);

    embed_h_k<<<(NTOK * 384 + 255) / 256, 256>>>(box, w1);

    // 2) x = relu(h @ w2) + cat
    hgemm_k<1, 64><<<dim3(DD / 128, NTOK / 64), 256, sm_64>>>(
        ghh, w2h, nullptr, cat, gx, nullptr, NTOK, DD, 384);

    ln_k<<<NTOK, 256>>>(gx, ln1g, ln1b, ghnh);

    // 4) qkv = hn @ wqkv
    hgemm_k<0, 128><<<dim3(3 * DD / 128, NTOK / 128), 256, sm_128>>>(
        ghnh, qkh, nullptr, nullptr, gqkv, nullptr, NTOK, 3 * DD, DD);

    attn_k<<<BB * NHH, 160, ATT_SMEM>>>(gqkv, gatth);

    // 6) x = x + att @ wo + bo
    hgemm_k<2, 64><<<dim3(DD / 128, NTOK / 64), 256, sm_64>>>(
        gatth, woh, bo, gx, gx, nullptr, NTOK, DD, DD);

    ln_k<<<NTOK, 256>>>(gx, ln2g, ln2b, ghnh);

    // 8) ffn = gelu(hn @ wfc1 + bfc1) -> fp16
    hgemm_k<3, 128><<<dim3(4 * DD / 128, NTOK / 128), 256, sm_128>>>(
        ghnh, f1h, bfc1, nullptr, nullptr, gffnh, NTOK, 4 * DD, DD);

    // 9) x = x + ffn @ wfc2 + bfc2
    hgemm_k<2, 64><<<dim3(DD / 128, NTOK / 64), 256, sm_64>>>(
        gffnh, f2h, bfc2, gx, gx, nullptr, NTOK, DD, 4 * DD);

    grid_k<<<BB * 8 * GH * GW, 256>>>(box, out);
}

// round 9
// speedup vs baseline: 4.1418x; 1.0048x over previous
#include <cuda_runtime.h>
#include <cuda_fp16.h>
#include <math.h>
#include <stdint.h>

#define BB   16
#define TT   16
#define OO   10
#define LL   160      // T*O
#define DD   768
#define NHH  12
#define DHH  64
#define GH   14
#define GW   14
#define NTOK (BB*LL)  // 2560

// ---------------- scratch (device globals; no runtime alloc allowed) --------
__device__ float g_x  [NTOK*DD];       // residual stream, fp32
__device__ float g_qkv[NTOK*3*DD];     // fp32, read by attention

__device__ __half g_h_hi  [NTOK*384];
__device__ __half g_hn_hi [NTOK*DD];
__device__ __half g_att_hi[NTOK*DD];
__device__ __half g_ffn_hi[NTOK*4*DD];

// transposed weights [N][K], single fp16 (round-to-nearest)
__device__ __half g_w2h  [DD*384];
__device__ __half g_qkvh [3*DD*DD];
__device__ __half g_woh  [DD*DD];
__device__ __half g_fc1h [4*DD*DD];
__device__ __half g_fc2h [DD*4*DD];

// ============================ helpers ========================================
__device__ __forceinline__ uint32_t smem_u32(const void* p) {
    uint32_t a;
    asm("{ .reg .u64 t; cvta.to.shared.u64 t, %1; cvt.u32.u64 %0, t; }" : "=r"(a) : "l"(p));
    return a;
}
__device__ __forceinline__ void split_f16(float v, __half& h, __half& l) {
    h = __float2half_rn(v);
    l = __float2half_rn(v - __half2float(h));
}
__device__ __forceinline__ uint32_t h2pack(__half a, __half b) {
    __half2 h; h.x = a; h.y = b;
    return *(uint32_t*)&h;
}
__device__ __forceinline__ void ldsm4(uint32_t* r, uint32_t addr) {
    asm volatile("ldmatrix.sync.aligned.m8n8.x4.shared.b16 {%0,%1,%2,%3}, [%4];"
        : "=r"(r[0]), "=r"(r[1]), "=r"(r[2]), "=r"(r[3]) : "r"(addr));
}
__device__ __forceinline__ void mma16816(float* c, const uint32_t* a, uint32_t b0, uint32_t b1) {
    asm volatile(
        "mma.sync.aligned.m16n8k16.row.col.f32.f16.f16.f32 "
        "{%0,%1,%2,%3}, {%4,%5,%6,%7}, {%8,%9}, {%0,%1,%2,%3};"
        : "+f"(c[0]), "+f"(c[1]), "+f"(c[2]), "+f"(c[3])
        : "r"(a[0]), "r"(a[1]), "r"(a[2]), "r"(a[3]), "r"(b0), "r"(b1));
}
__device__ __forceinline__ void cpa16(uint32_t dst, const void* src) {
    asm volatile("cp.async.cg.shared.global [%0], [%1], 16;" :: "r"(dst), "l"(src) : "memory");
}
#define CP_COMMIT() asm volatile("cp.async.commit_group;" ::: "memory")
#define CP_WAIT0()  asm volatile("cp.async.wait_group 0;" ::: "memory")
#define CP_WAIT1()  asm volatile("cp.async.wait_group 1;" ::: "memory")

// ---------------- fused: weight transpose (fp16 RN) + embed stage 1 ---------
// blocks [0,7200): W[K][N] -> Th [N][K].  blocks [7200,11040): h = relu(box@w1)
__global__ void fused_pre_k(
    const float* __restrict__ w2, const float* __restrict__ wqkv,
    const float* __restrict__ wo, const float* __restrict__ wfc1,
    const float* __restrict__ wfc2,
    const float* __restrict__ box, const float* __restrict__ w1)
{
    int b = blockIdx.x;
    if (b >= 7200) {
        int idx = (b - 7200) * 256 + threadIdx.y * 32 + threadIdx.x;
        int m = idx / 384, j = idx - m * 384;
        const float* bx = box + m * 4;
        float acc = bx[0] * w1[j] + bx[1] * w1[384 + j] + bx[2] * w1[768 + j] + bx[3] * w1[1152 + j];
        g_h_hi[idx] = __float2half_rn(fmaxf(acc, 0.0f));
        return;
    }
    const float* W; __half* Th; int K, N, nbx;
    if (b < 288)       { W = w2;   Th = g_w2h;  K = 384;  N = 768;  nbx = 24; }
    else if (b < 2016) { b -= 288;  W = wqkv; Th = g_qkvh; K = 768;  N = 2304; nbx = 72; }
    else if (b < 2592) { b -= 2016; W = wo;   Th = g_woh;  K = 768;  N = 768;  nbx = 24; }
    else if (b < 4896) { b -= 2592; W = wfc1; Th = g_fc1h; K = 768;  N = 3072; nbx = 96; }
    else               { b -= 4896; W = wfc2; Th = g_fc2h; K = 3072; N = 768;  nbx = 24; }
    int nb = (b % nbx) * 32, kb = (b / nbx) * 32;

    __shared__ float t[32][33];
    int x = threadIdx.x, y = threadIdx.y;   // (32, 8)
#pragma unroll
    for (int i = 0; i < 32; i += 8)
        t[y + i][x] = W[(size_t)(kb + y + i) * N + nb + x];
    __syncthreads();
#pragma unroll
    for (int i = 0; i < 32; i += 8)
        Th[(size_t)(nb + y + i) * K + kb + x] = __float2half_rn(t[x][y + i]);
}

// ================= HMMA fp16 GEMM, 3-stage cp.async ring, KC=64 =============
// C[M,N] = epi(A @ B^T). A [M][K] fp16, B [N][K] fp16.
// CTA tile TM x 128, 8 warps (2m x 4n). Rows 64 halves + 16B pad = 144B stride.
// EPI: 0 plain fp32; 1 relu + res[(m%LL)*N+n]; 2 +bias+res[m*N+n]; 3 +bias, gelu -> fp16
template<int EPI, int TM>
__global__ void __launch_bounds__(256)
hgemm_k(const __half* __restrict__ Ah, const __half* __restrict__ Bh16,
        const float* __restrict__ bias, const float* __restrict__ res,
        float* __restrict__ Cf, __half* __restrict__ Chi,
        int M, int N, int K)
{
    extern __shared__ __align__(16) __half smbuf[];
    constexpr int MT = TM / 32;
    constexpr uint32_t offB  = (uint32_t)TM * 144;
    constexpr uint32_t STG_B = (uint32_t)(TM + 128) * 144;

    const int tid = threadIdx.x;
    const int wid = tid >> 5, lane = tid & 31;
    const int wm = wid >> 2, wn = wid & 3;
    const int m0 = blockIdx.y * TM, n0 = blockIdx.x * 128;
    const uint32_t smb = smem_u32(smbuf);

    const int nch = K >> 6;

    auto load_stage = [&](int st, int kb) {
        uint32_t sb = smb + (uint32_t)st * STG_B;
#pragma unroll
        for (int s = tid; s < TM * 8; s += 256) {
            int row = s >> 3, seg = s & 7;
            uint32_t d = sb + (uint32_t)(row * 144 + seg * 16);
            cpa16(d, Ah + (size_t)(m0 + row) * K + kb + seg * 8);
        }
#pragma unroll
        for (int s = tid; s < 1024; s += 256) {
            int row = s >> 3, seg = s & 7;
            uint32_t d = sb + (uint32_t)(row * 144 + seg * 16);
            cpa16(d + offB, Bh16 + (size_t)(n0 + row) * K + kb + seg * 8);
        }
    };

    const uint32_t a_lo = (uint32_t)(lane & 15) * 144 + (uint32_t)(lane >> 4) * 16;
    const uint32_t a_wb = (uint32_t)(wm * (TM / 2)) * 144;
    const uint32_t b_wb = (uint32_t)(wn * 32) * 144;

    float c[MT][4][4] = {};

    load_stage(0, 0);
    CP_COMMIT();
    load_stage(1, 64);           // all GEMMs here have nch >= 6
    CP_COMMIT();

    int st = 0;
    for (int ch = 0; ch < nch; ch++) {
        if (ch < nch - 1) { CP_WAIT1(); } else { CP_WAIT0(); }
        __syncthreads();         // all warps done reading the stage we overwrite next
        if (ch + 2 < nch) {
            int ns = st + 2; if (ns >= 3) ns -= 3;
            load_stage(ns, (ch + 2) << 6);
            CP_COMMIT();
        }
        uint32_t sb = smb + (uint32_t)st * STG_B;
#pragma unroll
        for (int ks = 0; ks < 4; ks++) {
            uint32_t koff = ks * 32;
            uint32_t ah[MT][4], bh[2][4];
#pragma unroll
            for (int mt = 0; mt < MT; mt++) {
                uint32_t off = a_wb + (uint32_t)(mt * 16) * 144 + a_lo + koff;
                ldsm4(ah[mt], sb + off);
            }
#pragma unroll
            for (int p = 0; p < 2; p++) {
                uint32_t off = b_wb + (uint32_t)(p * 16) * 144 + a_lo + koff;
                ldsm4(bh[p], sb + offB + off);
            }
#pragma unroll
            for (int mt = 0; mt < MT; mt++) {
#pragma unroll
                for (int p = 0; p < 2; p++) {
#pragma unroll
                    for (int s = 0; s < 2; s++) {
                        int nt = p * 2 + s;
                        mma16816(c[mt][nt], ah[mt], bh[p][s], bh[p][s + 2]);
                    }
                }
            }
        }
        if (++st == 3) st = 0;
    }

    const int rbase = m0 + wm * (TM / 2) + (lane >> 2);
    const int cbase = n0 + wn * 32 + (lane & 3) * 2;
#pragma unroll
    for (int mt = 0; mt < MT; mt++) {
#pragma unroll
        for (int rr = 0; rr < 2; rr++) {
            int m = rbase + mt * 16 + rr * 8;
#pragma unroll
            for (int nt = 0; nt < 4; nt++) {
                int n = cbase + nt * 8;
                float v0 = c[mt][nt][rr * 2 + 0];
                float v1 = c[mt][nt][rr * 2 + 1];
                if (EPI == 1) {
                    const float* rp = res + (size_t)(m % LL) * N + n;
                    v0 = fmaxf(v0, 0.0f) + rp[0];
                    v1 = fmaxf(v1, 0.0f) + rp[1];
                    *(float2*)(Cf + (size_t)m * N + n) = make_float2(v0, v1);
                } else if (EPI == 2) {
                    const float* rp = res + (size_t)m * N + n;
                    v0 += bias[n] + rp[0];
                    v1 += bias[n + 1] + rp[1];
                    *(float2*)(Cf + (size_t)m * N + n) = make_float2(v0, v1);
                } else if (EPI == 3) {
                    v0 += bias[n];
                    v1 += bias[n + 1];
                    v0 = 0.5f * v0 * (1.0f + erff(v0 * 0.70710678118654752f));
                    v1 = 0.5f * v1 * (1.0f + erff(v1 * 0.70710678118654752f));
                    *(__half2*)(Chi + (size_t)m * N + n) =
                        __halves2half2(__float2half_rn(v0), __float2half_rn(v1));
                } else {
                    *(float2*)(Cf + (size_t)m * N + n) = make_float2(v0, v1);
                }
            }
        }
    }
}

// ================= HMMA attention: one block per (b,h), 160 threads =========
#define KSTR 72
#define VSTR 168
#define ATT_SMEM ((2*160*KSTR + 2*64*VSTR) * 2)   // 89088 bytes

__global__ void __launch_bounds__(160)
attn_k(const float* __restrict__ qkv, __half* __restrict__ Yhi)
{
    extern __shared__ __half smh[];
    __half* sKh = smh;
    __half* sKl = smh + 160 * KSTR;
    __half* sVh = smh + 2 * 160 * KSTR;
    __half* sVl = smh + 2 * 160 * KSTR + 64 * VSTR;

    const int bh = blockIdx.x;
    const int b = bh / NHH, h = bh - b * NHH;
    const int tid = threadIdx.x;
    const int wid = tid >> 5, lane = tid & 31;
    const int g = lane >> 2, t = lane & 3;

    for (int idx = tid; idx < 160 * 64; idx += 160) {
        int row = idx >> 6, col = idx & 63;
        size_t base = (size_t)(b * LL + row) * 2304 + h * 64 + col;
        float kv = qkv[base + 768];
        float vv = qkv[base + 1536];
        __half khh, kll; split_f16(kv, khh, kll);
        sKh[row * KSTR + col] = khh;
        sKl[row * KSTR + col] = kll;
        __half vhh, vll; split_f16(vv, vhh, vll);
        sVh[col * VSTR + row] = vhh;
        sVl[col * VSTR + row] = vll;
    }
    __syncthreads();

    const uint32_t kh_b = smem_u32(sKh), kl_b = smem_u32(sKl);
    const uint32_t vh_b = smem_u32(sVh), vl_b = smem_u32(sVl);
    const uint32_t lrow = (uint32_t)(lane & 15);
    const uint32_t lseg = (uint32_t)(lane >> 4) * 16;

#pragma unroll
    for (int mi = 0; mi < 2; mi++) {
        const int mt = wid * 2 + mi;
        const size_t qrow0 = (size_t)(b * LL + mt * 16 + g) * 2304 + h * 64;
        const size_t qrow1 = qrow0 + 8 * 2304;

        uint32_t qh[4][4], ql[4][4];
#pragma unroll
        for (int kt = 0; kt < 4; kt++) {
            int c0 = kt * 16 + 2 * t;
            float2 x0 = *(const float2*)(qkv + qrow0 + c0);
            float2 x1 = *(const float2*)(qkv + qrow1 + c0);
            float2 x2 = *(const float2*)(qkv + qrow0 + c0 + 8);
            float2 x3 = *(const float2*)(qkv + qrow1 + c0 + 8);
            float f[4][2] = {{x0.x * 0.125f, x0.y * 0.125f}, {x1.x * 0.125f, x1.y * 0.125f},
                             {x2.x * 0.125f, x2.y * 0.125f}, {x3.x * 0.125f, x3.y * 0.125f}};
#pragma unroll
            for (int a = 0; a < 4; a++) {
                __half h0, l0, h1, l1;
                split_f16(f[a][0], h0, l0);
                split_f16(f[a][1], h1, l1);
                qh[kt][a] = h2pack(h0, h1);
                ql[kt][a] = h2pack(l0, l1);
            }
        }

        float c[20][4];
#pragma unroll
        for (int nt = 0; nt < 20; nt++)
#pragma unroll
            for (int e = 0; e < 4; e++) c[nt][e] = 0.f;

        for (int n2 = 0; n2 < 10; n2++) {
            uint32_t roff = (uint32_t)(n2 * 16) * 144 + lrow * 144 + lseg;
#pragma unroll
            for (int kt = 0; kt < 4; kt++) {
                uint32_t kfh[4], kfl[4];
                ldsm4(kfh, kh_b + roff + kt * 32);
                ldsm4(kfl, kl_b + roff + kt * 32);
#pragma unroll
                for (int s = 0; s < 2; s++) {
                    float* cc = c[n2 * 2 + s];
                    mma16816(cc, qh[kt], kfh[s], kfh[s + 2]);
                    mma16816(cc, ql[kt], kfh[s], kfh[s + 2]);
                    mma16816(cc, qh[kt], kfl[s], kfl[s + 2]);
                }
            }
        }

        float m0 = -1e30f, m1 = -1e30f;
#pragma unroll
        for (int nt = 0; nt < 20; nt++) {
            m0 = fmaxf(m0, fmaxf(c[nt][0], c[nt][1]));
            m1 = fmaxf(m1, fmaxf(c[nt][2], c[nt][3]));
        }
#pragma unroll
        for (int off = 1; off <= 2; off <<= 1) {
            m0 = fmaxf(m0, __shfl_xor_sync(0xffffffffu, m0, off));
            m1 = fmaxf(m1, __shfl_xor_sync(0xffffffffu, m1, off));
        }
        float s0 = 0.f, s1 = 0.f;
#pragma unroll
        for (int nt = 0; nt < 20; nt++) {
            c[nt][0] = __expf(c[nt][0] - m0);
            c[nt][1] = __expf(c[nt][1] - m0);
            c[nt][2] = __expf(c[nt][2] - m1);
            c[nt][3] = __expf(c[nt][3] - m1);
            s0 += c[nt][0] + c[nt][1];
            s1 += c[nt][2] + c[nt][3];
        }
#pragma unroll
        for (int off = 1; off <= 2; off <<= 1) {
            s0 += __shfl_xor_sync(0xffffffffu, s0, off);
            s1 += __shfl_xor_sync(0xffffffffu, s1, off);
        }
        const float inv0 = 1.0f / s0, inv1 = 1.0f / s1;

        float o[8][4];
#pragma unroll
        for (int nt = 0; nt < 8; nt++)
#pragma unroll
            for (int e = 0; e < 4; e++) o[nt][e] = 0.f;

        for (int k2 = 0; k2 < 10; k2++) {
            uint32_t ph[4], pl[4];
            {
                const float* ca = c[2 * k2];
                const float* cb = c[2 * k2 + 1];
                __half ha, la, hb, lb;
                split_f16(ca[0], ha, la); split_f16(ca[1], hb, lb);
                ph[0] = h2pack(ha, hb); pl[0] = h2pack(la, lb);
                split_f16(ca[2], ha, la); split_f16(ca[3], hb, lb);
                ph[1] = h2pack(ha, hb); pl[1] = h2pack(la, lb);
                split_f16(cb[0], ha, la); split_f16(cb[1], hb, lb);
                ph[2] = h2pack(ha, hb); pl[2] = h2pack(la, lb);
                split_f16(cb[2], ha, la); split_f16(cb[3], hb, lb);
                ph[3] = h2pack(ha, hb); pl[3] = h2pack(la, lb);
            }
#pragma unroll
            for (int n2v = 0; n2v < 4; n2v++) {
                uint32_t roff = (uint32_t)(n2v * 16) * 336 + lrow * 336 + lseg + k2 * 32;
                uint32_t vfh[4], vfl[4];
                ldsm4(vfh, vh_b + roff);
                ldsm4(vfl, vl_b + roff);
#pragma unroll
                for (int s = 0; s < 2; s++) {
                    float* oo = o[n2v * 2 + s];
                    mma16816(oo, ph, vfh[s], vfh[s + 2]);
                    mma16816(oo, pl, vfh[s], vfh[s + 2]);
                    mma16816(oo, ph, vfl[s], vfl[s + 2]);
                }
            }
        }

        const size_t row0 = (size_t)(b * LL + mt * 16 + g) * DD + h * 64;
        const size_t row1 = row0 + (size_t)8 * DD;
#pragma unroll
        for (int nt = 0; nt < 8; nt++) {
            int col = nt * 8 + 2 * t;
            *(__half2*)(Yhi + row0 + col) =
                __halves2half2(__float2half_rn(o[nt][0] * inv0), __float2half_rn(o[nt][1] * inv0));
            *(__half2*)(Yhi + row1 + col) =
                __halves2half2(__float2half_rn(o[nt][2] * inv1), __float2half_rn(o[nt][3] * inv1));
        }
    }
}

// ---------------- layernorm: one block per row, fp16 output -----------------
__global__ void ln_k(const float* __restrict__ X, const float* __restrict__ g,
                     const float* __restrict__ b, __half* __restrict__ Yhi)
{
    int row = blockIdx.x;
    const float* x = X + (size_t)row * DD;
    int tid = threadIdx.x;
    float v[3];
    float s = 0.f, sq = 0.f;
#pragma unroll
    for (int r = 0; r < 3; r++) {
        v[r] = x[tid + r * 256];
        s += v[r];
        sq += v[r] * v[r];
    }
    __shared__ float red0[8], red1[8];
#pragma unroll
    for (int off = 16; off; off >>= 1) {
        s += __shfl_down_sync(0xffffffffu, s, off);
        sq += __shfl_down_sync(0xffffffffu, sq, off);
    }
    if ((tid & 31) == 0) { red0[tid >> 5] = s; red1[tid >> 5] = sq; }
    __syncthreads();
    s = 0.f; sq = 0.f;
#pragma unroll
    for (int i = 0; i < 8; i++) { s += red0[i]; sq += red1[i]; }
    float mean = s * (1.0f / DD);
    float var = sq * (1.0f / DD) - mean * mean;
    float rstd = rsqrtf(var + 1e-5f);
#pragma unroll
    for (int r = 0; r < 3; r++) {
        int c = tid + r * 256;
        float y = (v[r] - mean) * rstd * g[c] + b[c];
        Yhi[(size_t)row * DD + c] = __float2half_rn(y);
    }
}

// ---------------- box-mask scatter + temporal mean ---------------------------
__global__ void grid_k(const float* __restrict__ box, float* __restrict__ out)
{
    int blk = blockIdx.x;
    int w = blk % GW;
    int hh = (blk / GW) % GH;
    int tg = (blk / (GW * GH)) & 7;
    int b = blk / (GW * GH * 8);
    int tid = threadIdx.x;

    __shared__ float flg[20];
    if (tid < 20) {
        int t = tg * 2 + tid / 10;
        int o = tid % 10;
        const float* bx = box + (size_t)((b * TT + t) * OO + o) * 4;
        float x1 = fminf(bx[0], bx[2]), x2 = fmaxf(bx[0], bx[2]);
        float y1 = fminf(bx[1], bx[3]), y2 = fmaxf(bx[1], bx[3]);
        float cy = (hh + 0.5f) / 14.0f;
        float cx = (w + 0.5f) / 14.0f;
        flg[tid] = (cy >= y1 && cy <= y2 && cx >= x1 && cx <= x2) ? 1.0f : 0.0f;
    }
    __syncthreads();

    float a0 = 0.f, a1 = 0.f, a2 = 0.f;
#pragma unroll
    for (int e = 0; e < 20; e++) {
        if (flg[e] > 0.f) {
            const float* f = g_x + (size_t)(b * LL + (tg * 2 + e / 10) * OO + (e % 10)) * DD + tid;
            a0 += f[0];
            a1 += f[256];
            a2 += f[512];
        }
    }
    size_t ob = (size_t)blk * DD + tid;
    out[ob]       = 0.5f * a0;
    out[ob + 256] = 0.5f * a1;
    out[ob + 512] = 0.5f * a2;
}

// ---------------- launch ------------------------------------------------------
extern "C" void kernel_launch(void* const* d_in, const int* in_sizes, int n_in,
                              void* d_out, int out_size)
{
    const float* box  = (const float*)d_in[0];
    const float* cat  = (const float*)d_in[1];
    const float* w1   = (const float*)d_in[2];
    const float* w2   = (const float*)d_in[3];
    const float* ln1g = (const float*)d_in[4];
    const float* ln1b = (const float*)d_in[5];
    const float* wqkv = (const float*)d_in[6];
    const float* wo   = (const float*)d_in[7];
    const float* bo   = (const float*)d_in[8];
    const float* ln2g = (const float*)d_in[9];
    const float* ln2b = (const float*)d_in[10];
    const float* wfc1 = (const float*)d_in[11];
    const float* bfc1 = (const float*)d_in[12];
    const float* wfc2 = (const float*)d_in[13];
    const float* bfc2 = (const float*)d_in[14];
    float* out = (float*)d_out;

    float *gx, *gqkv;
    __half *ghh, *ghnh, *gatth, *gffnh;
    __half *w2h, *qkh, *woh, *f1h, *f2h;
    cudaGetSymbolAddress((void**)&gx,    g_x);
    cudaGetSymbolAddress((void**)&gqkv,  g_qkv);
    cudaGetSymbolAddress((void**)&ghh,   g_h_hi);
    cudaGetSymbolAddress((void**)&ghnh,  g_hn_hi);
    cudaGetSymbolAddress((void**)&gatth, g_att_hi);
    cudaGetSymbolAddress((void**)&gffnh, g_ffn_hi);
    cudaGetSymbolAddress((void**)&w2h,   g_w2h);
    cudaGetSymbolAddress((void**)&qkh,   g_qkvh);
    cudaGetSymbolAddress((void**)&woh,   g_woh);
    cudaGetSymbolAddress((void**)&f1h,   g_fc1h);
    cudaGetSymbolAddress((void**)&f2h,   g_fc2h);

    cudaFuncSetAttribute(attn_k, cudaFuncAttributeMaxDynamicSharedMemorySize, ATT_SMEM);

    // smem: (TM+128)*144*3 stages
    const int sm_64  = (64 + 128) * 144 * 3;    // 82944
    const int sm_128 = (128 + 128) * 144 * 3;   // 110592
    cudaFuncSetAttribute((const void*)hgemm_k<1, 64>,  cudaFuncAttributeMaxDynamicSharedMemorySize, sm_64);
    cudaFuncSetAttribute((const void*)hgemm_k<2, 64>,  cudaFuncAttributeMaxDynamicSharedMemorySize, sm_64);
    cudaFuncSetAttribute((const void*)hgemm_k<0, 128>, cudaFuncAttributeMaxDynamicSharedMemorySize, sm_128);
    cudaFuncSetAttribute((const void*)hgemm_k<3, 128>, cudaFuncAttributeMaxDynamicSharedMemorySize, sm_128);

    // fused weight transpose + embed (blocks 7200..11039)
    fused_pre_k<<<11040, dim3(32, 8)>>>(w2, wqkv, wo, wfc1, wfc2, box, w1);

    // 2) x = relu(h @ w2) + cat
    hgemm_k<1, 64><<<dim3(DD / 128, NTOK / 64), 256, sm_64>>>(
        ghh, w2h, nullptr, cat, gx, nullptr, NTOK, DD, 384);

    ln_k<<<NTOK, 256>>>(gx, ln1g, ln1b, ghnh);

    // 4) qkv = hn @ wqkv
    hgemm_k<0, 128><<<dim3(3 * DD / 128, NTOK / 128), 256, sm_128>>>(
        ghnh, qkh, nullptr, nullptr, gqkv, nullptr, NTOK, 3 * DD, DD);

    attn_k<<<BB * NHH, 160, ATT_SMEM>>>(gqkv, gatth);

    // 6) x = x + att @ wo + bo
    hgemm_k<2, 64><<<dim3(DD / 128, NTOK / 64), 256, sm_64>>>(
        gatth, woh, bo, gx, gx, nullptr, NTOK, DD, DD);

    ln_k<<<NTOK, 256>>>(gx, ln2g, ln2b, ghnh);

    // 8) ffn = gelu(hn @ wfc1 + bfc1) -> fp16
    hgemm_k<3, 128><<<dim3(4 * DD / 128, NTOK / 128), 256, sm_128>>>(
        ghnh, f1h, bfc1, nullptr, nullptr, gffnh, NTOK, 4 * DD, DD);

    // 9) x = x + ffn @ wfc2 + bfc2
    hgemm_k<2, 64><<<dim3(DD / 128, NTOK / 64), 256, sm_64>>>(
        gffnh, f2h, bfc2, gx, gx, nullptr, NTOK, DD, 4 * DD);

    grid_k<<<BB * 8 * GH * GW, 256>>>(box, out);
}